// round 1
// baseline (speedup 1.0000x reference)
#include <cuda_runtime.h>
#include <math.h>

#define S_LEN 2048
#define DIM 4096
#define NH 32
#define NKV 8
#define HD 128
#define KV_DIM 1024

// Scratch (allocation-free rule: __device__ globals)
__device__ float g_q[S_LEN * DIM];
__device__ float g_k[S_LEN * KV_DIM];
__device__ float g_v[S_LEN * KV_DIM];
__device__ float g_attn[S_LEN * DIM];

// ---------------------------------------------------------------------------
// SGEMM: C[M,N] = A[M,K] * B[N,K]^T   (A,B row-major; computes x @ W^T)
// 128x128x16 tile, 256 threads, 8x8 microtile per thread.
// ---------------------------------------------------------------------------
#define BM 128
#define BN 128
#define BKK 16

__global__ __launch_bounds__(256, 2)
void sgemm_nt(const float* __restrict__ A, const float* __restrict__ B,
              float* __restrict__ C, int M, int N, int K) {
    __shared__ float As[BKK][BM + 4];
    __shared__ float Bs[BKK][BN + 4];
    const int tid = threadIdx.x;
    const int tx = tid & 15, ty = tid >> 4;
    const float* Ab = A + (size_t)blockIdx.y * BM * K;
    const float* Bb = B + (size_t)blockIdx.x * BN * K;

    float acc[8][8];
#pragma unroll
    for (int i = 0; i < 8; i++)
#pragma unroll
        for (int j = 0; j < 8; j++) acc[i][j] = 0.f;

    for (int kt = 0; kt < K; kt += BKK) {
#pragma unroll
        for (int t = 0; t < 2; t++) {
            int idx = tid + t * 256;
            int row = idx >> 2;
            int c = (idx & 3) << 2;
            float4 a4 = *(const float4*)(Ab + (size_t)row * K + kt + c);
            As[c + 0][row] = a4.x; As[c + 1][row] = a4.y;
            As[c + 2][row] = a4.z; As[c + 3][row] = a4.w;
            float4 b4 = *(const float4*)(Bb + (size_t)row * K + kt + c);
            Bs[c + 0][row] = b4.x; Bs[c + 1][row] = b4.y;
            Bs[c + 2][row] = b4.z; Bs[c + 3][row] = b4.w;
        }
        __syncthreads();
#pragma unroll
        for (int k = 0; k < BKK; k++) {
            float a[8], b[8];
            *(float4*)(a)     = *(const float4*)&As[k][ty * 8];
            *(float4*)(a + 4) = *(const float4*)&As[k][ty * 8 + 4];
            *(float4*)(b)     = *(const float4*)&Bs[k][tx * 8];
            *(float4*)(b + 4) = *(const float4*)&Bs[k][tx * 8 + 4];
#pragma unroll
            for (int i = 0; i < 8; i++)
#pragma unroll
                for (int j = 0; j < 8; j++)
                    acc[i][j] += a[i] * b[j];
        }
        __syncthreads();
    }

    float* Cb = C + (size_t)(blockIdx.y * BM + ty * 8) * N + blockIdx.x * BN + tx * 8;
#pragma unroll
    for (int i = 0; i < 8; i++) {
        *(float4*)(Cb + (size_t)i * N)     = make_float4(acc[i][0], acc[i][1], acc[i][2], acc[i][3]);
        *(float4*)(Cb + (size_t)i * N + 4) = make_float4(acc[i][4], acc[i][5], acc[i][6], acc[i][7]);
    }
}

// ---------------------------------------------------------------------------
// Per-head RMSNorm + RoPE, in place. grid = (S, nheads), 128 threads (= HD).
// ---------------------------------------------------------------------------
__global__ void rmsnorm_rope_kernel(float* __restrict__ buf, int rowStride,
                                    const float* __restrict__ w,
                                    const float* __restrict__ cosp,
                                    const float* __restrict__ sinp) {
    const int s = blockIdx.x, h = blockIdx.y, d = threadIdx.x;
    float* p = buf + (size_t)s * rowStride + h * HD;
    float v = p[d];
    float sq = v * v;
#pragma unroll
    for (int off = 16; off > 0; off >>= 1)
        sq += __shfl_xor_sync(0xffffffffu, sq, off);
    __shared__ float red[4];
    __shared__ float xs[HD];
    if ((d & 31) == 0) red[d >> 5] = sq;
    __syncthreads();
    float sum = red[0] + red[1] + red[2] + red[3];
    float r = rsqrtf(sum * (1.0f / HD) + 1e-6f);
    float xn = v * r * w[d];
    xs[d] = xn;
    __syncthreads();
    float rot = (d < 64) ? -xs[d + 64] : xs[d - 64];
    p[d] = xn * cosp[(size_t)s * HD + d] + rot * sinp[(size_t)s * HD + d];
}

// ---------------------------------------------------------------------------
// Flash attention, fp32, causal, GQA (kv head = h/4).
// BLOCK_M = BLOCK_N = 64, 256 threads. Each thread: 4 S-rows x 4 S-cols,
// O microtile 4 rows x 8 cols. Dynamic smem ~81.5 KB, 2 CTA/SM.
// ---------------------------------------------------------------------------
#define FM 64
#define FN 64
#define QS 129   // sQ row stride (odd -> conflict-free scalar reads)
#define KS 129   // sK row stride
#define VS 132   // sV row stride (mult of 4 -> float4 reads)
#define PS 65    // sP row stride

__global__ __launch_bounds__(256, 2)
void flash_attn(const float* __restrict__ Q, const float* __restrict__ K,
                const float* __restrict__ V, float* __restrict__ O) {
    extern __shared__ float sm[];
    float* sQ  = sm;               // FM * QS
    float* sKV = sm + FM * QS;     // FM * VS (K uses stride KS, V uses VS)
    float* sP  = sKV + FM * VS;    // FM * PS

    const int tid = threadIdx.x;
    const int tx = tid & 15, ty = tid >> 4;
    const int mt = blockIdx.x, h = blockIdx.y;
    const int kvh = h >> 2;
    const int m0 = mt * FM;

    // Load Q tile (64 x 128) for this head
#pragma unroll
    for (int t = 0; t < 8; t++) {
        int idx = tid + t * 256;
        int r = idx >> 5;
        int c = (idx & 31) << 2;
        float4 q4 = *(const float4*)(Q + (size_t)(m0 + r) * DIM + h * HD + c);
        sQ[r * QS + c + 0] = q4.x; sQ[r * QS + c + 1] = q4.y;
        sQ[r * QS + c + 2] = q4.z; sQ[r * QS + c + 3] = q4.w;
    }

    float o[4][8];
    float mi[4], li[4];
#pragma unroll
    for (int i = 0; i < 4; i++) {
        mi[i] = -1e30f; li[i] = 0.f;
#pragma unroll
        for (int j = 0; j < 8; j++) o[i][j] = 0.f;
    }

    const float sc = 0.08838834764831845f;  // 1/sqrt(128)

    for (int nt = 0; nt <= mt; nt++) {
        const int n0 = nt * FN;
        // Load K tile (64 x 128), kv head
#pragma unroll
        for (int t = 0; t < 8; t++) {
            int idx = tid + t * 256;
            int r = idx >> 5;
            int c = (idx & 31) << 2;
            float4 k4 = *(const float4*)(K + (size_t)(n0 + r) * KV_DIM + kvh * HD + c);
            sKV[r * KS + c + 0] = k4.x; sKV[r * KS + c + 1] = k4.y;
            sKV[r * KS + c + 2] = k4.z; sKV[r * KS + c + 3] = k4.w;
        }
        __syncthreads();

        // S = Q K^T  (4x4 per thread)
        float s_[4][4];
#pragma unroll
        for (int i = 0; i < 4; i++)
#pragma unroll
            for (int j = 0; j < 4; j++) s_[i][j] = 0.f;

#pragma unroll 4
        for (int d = 0; d < HD; d++) {
            float qv[4], kv[4];
#pragma unroll
            for (int i = 0; i < 4; i++) qv[i] = sQ[(ty * 4 + i) * QS + d];
#pragma unroll
            for (int j = 0; j < 4; j++) kv[j] = sKV[(tx * 4 + j) * KS + d];
#pragma unroll
            for (int i = 0; i < 4; i++)
#pragma unroll
                for (int j = 0; j < 4; j++)
                    s_[i][j] += qv[i] * kv[j];
        }

        // scale + causal mask
#pragma unroll
        for (int i = 0; i < 4; i++) {
            int row = ty * 4 + i;
#pragma unroll
            for (int j = 0; j < 4; j++) {
                s_[i][j] *= sc;
                if (nt == mt) {
                    int col = tx * 4 + j;
                    if (col > row) s_[i][j] = -1e30f;
                }
            }
        }

        // online softmax per row (16 lanes share a row -> width-16 shuffles)
#pragma unroll
        for (int i = 0; i < 4; i++) {
            float mloc = fmaxf(fmaxf(s_[i][0], s_[i][1]), fmaxf(s_[i][2], s_[i][3]));
#pragma unroll
            for (int off = 1; off < 16; off <<= 1)
                mloc = fmaxf(mloc, __shfl_xor_sync(0xffffffffu, mloc, off));
            float mnew = fmaxf(mi[i], mloc);
            float corr = __expf(mi[i] - mnew);
            float rs = 0.f;
#pragma unroll
            for (int j = 0; j < 4; j++) {
                float p = __expf(s_[i][j] - mnew);
                s_[i][j] = p;
                rs += p;
            }
#pragma unroll
            for (int off = 1; off < 16; off <<= 1)
                rs += __shfl_xor_sync(0xffffffffu, rs, off);
            li[i] = li[i] * corr + rs;
            mi[i] = mnew;
#pragma unroll
            for (int j = 0; j < 8; j++) o[i][j] *= corr;
#pragma unroll
            for (int j = 0; j < 4; j++)
                sP[(ty * 4 + i) * PS + tx * 4 + j] = s_[i][j];
        }
        __syncthreads();

        // Load V tile into same buffer (stride VS)
#pragma unroll
        for (int t = 0; t < 8; t++) {
            int idx = tid + t * 256;
            int r = idx >> 5;
            int c = (idx & 31) << 2;
            float4 v4 = *(const float4*)(V + (size_t)(n0 + r) * KV_DIM + kvh * HD + c);
            sKV[r * VS + c + 0] = v4.x; sKV[r * VS + c + 1] = v4.y;
            sKV[r * VS + c + 2] = v4.z; sKV[r * VS + c + 3] = v4.w;
        }
        __syncthreads();

        // O += P * V
#pragma unroll 2
        for (int n = 0; n < FN; n++) {
            float pv[4];
#pragma unroll
            for (int i = 0; i < 4; i++) pv[i] = sP[(ty * 4 + i) * PS + n];
            float4 v0 = *(const float4*)&sKV[n * VS + tx * 8];
            float4 v1 = *(const float4*)&sKV[n * VS + tx * 8 + 4];
#pragma unroll
            for (int i = 0; i < 4; i++) {
                o[i][0] += pv[i] * v0.x; o[i][1] += pv[i] * v0.y;
                o[i][2] += pv[i] * v0.z; o[i][3] += pv[i] * v0.w;
                o[i][4] += pv[i] * v1.x; o[i][5] += pv[i] * v1.y;
                o[i][6] += pv[i] * v1.z; o[i][7] += pv[i] * v1.w;
            }
        }
        __syncthreads();
    }

    // Epilogue: normalize and store (layout [s, h*HD + d])
#pragma unroll
    for (int i = 0; i < 4; i++) {
        float inv = 1.f / li[i];
        int row = m0 + ty * 4 + i;
        float* op = O + (size_t)row * DIM + h * HD + tx * 8;
        *(float4*)(op)     = make_float4(o[i][0] * inv, o[i][1] * inv, o[i][2] * inv, o[i][3] * inv);
        *(float4*)(op + 4) = make_float4(o[i][4] * inv, o[i][5] * inv, o[i][6] * inv, o[i][7] * inv);
    }
}

// ---------------------------------------------------------------------------
extern "C" void kernel_launch(void* const* d_in, const int* in_sizes, int n_in,
                              void* d_out, int out_size) {
    const float* x    = (const float*)d_in[0];
    const float* cosp = (const float*)d_in[1];
    const float* sinp = (const float*)d_in[2];
    const float* wq   = (const float*)d_in[3];
    const float* wk   = (const float*)d_in[4];
    const float* wv   = (const float*)d_in[5];
    const float* wo   = (const float*)d_in[6];
    const float* qw   = (const float*)d_in[7];
    const float* kw   = (const float*)d_in[8];
    float* out = (float*)d_out;

    float *q, *k, *v, *attn;
    cudaGetSymbolAddress((void**)&q, g_q);
    cudaGetSymbolAddress((void**)&k, g_k);
    cudaGetSymbolAddress((void**)&v, g_v);
    cudaGetSymbolAddress((void**)&attn, g_attn);

    const int flash_smem = (FM * QS + FM * VS + FM * PS) * (int)sizeof(float);
    cudaFuncSetAttribute(flash_attn, cudaFuncAttributeMaxDynamicSharedMemorySize, flash_smem);

    // QKV projections
    sgemm_nt<<<dim3(DIM / BN, S_LEN / BM), 256>>>(x, wq, q, S_LEN, DIM, DIM);
    sgemm_nt<<<dim3(KV_DIM / BN, S_LEN / BM), 256>>>(x, wk, k, S_LEN, KV_DIM, DIM);
    sgemm_nt<<<dim3(KV_DIM / BN, S_LEN / BM), 256>>>(x, wv, v, S_LEN, KV_DIM, DIM);

    // RMSNorm + RoPE (q and k)
    rmsnorm_rope_kernel<<<dim3(S_LEN, NH), HD>>>(q, DIM, qw, cosp, sinp);
    rmsnorm_rope_kernel<<<dim3(S_LEN, NKV), HD>>>(k, KV_DIM, kw, cosp, sinp);

    // Attention
    flash_attn<<<dim3(S_LEN / FM, NH), 256, flash_smem>>>(q, k, v, attn);

    // Output projection
    sgemm_nt<<<dim3(DIM / BN, S_LEN / BM), 256>>>(attn, wo, out, S_LEN, DIM, DIM);
}

// round 2
// speedup vs baseline: 2.8842x; 2.8842x over previous
#include <cuda_runtime.h>
#include <math.h>

#define S_LEN 2048
#define DIM 4096
#define NH 32
#define NKV 8
#define HD 128
#define KV_DIM 1024

__device__ float g_q[S_LEN * DIM];
__device__ float g_k[S_LEN * KV_DIM];
__device__ float g_v[S_LEN * KV_DIM];
__device__ float g_attn[S_LEN * DIM];

__device__ __forceinline__ float f2tf(float x) {
    unsigned u;
    asm("cvt.rna.tf32.f32 %0, %1;" : "=r"(u) : "f"(x));
    return __uint_as_float(u);
}

__device__ __forceinline__ void mma_tf32(float c[4], const unsigned a[4], const unsigned b[2]) {
    asm volatile(
        "mma.sync.aligned.m16n8k8.row.col.f32.tf32.tf32.f32 "
        "{%0,%1,%2,%3},{%4,%5,%6,%7},{%8,%9},{%0,%1,%2,%3};"
        : "+f"(c[0]), "+f"(c[1]), "+f"(c[2]), "+f"(c[3])
        : "r"(a[0]), "r"(a[1]), "r"(a[2]), "r"(a[3]), "r"(b[0]), "r"(b[1]));
}

// ---------------------------------------------------------------------------
// tf32 GEMM: C[M,N] = A[M,K] @ B[N,K]^T.  128x128x32 CTA tile, 256 threads,
// 8 warps in 2x4 grid, each warp 64x32 (4x4 m16n8k8 tiles).
// smem natural layout [row][k], stride 36 (== 4 mod 32 -> conflict-free frags).
// ---------------------------------------------------------------------------
#define GBM 128
#define GBN 128
#define GBK 32
#define GST 36

__global__ __launch_bounds__(256, 2)
void gemm_tf32_nt(const float* __restrict__ A, const float* __restrict__ B,
                  float* __restrict__ C, int M, int N, int K) {
    __shared__ float As[GBM][GST];
    __shared__ float Bs[GBN][GST];
    const int tid = threadIdx.x, lane = tid & 31, warp = tid >> 5;
    const int wm = warp >> 2, wn = warp & 3;
    const int m_base = wm * 64, n_base = wn * 32;
    const float* Ab = A + (size_t)blockIdx.y * GBM * K;
    const float* Bb = B + (size_t)blockIdx.x * GBN * K;

    float acc[4][4][4];
#pragma unroll
    for (int i = 0; i < 4; i++)
#pragma unroll
        for (int j = 0; j < 4; j++)
#pragma unroll
            for (int r = 0; r < 4; r++) acc[i][j][r] = 0.f;

    for (int kt = 0; kt < K; kt += GBK) {
#pragma unroll
        for (int t = 0; t < 4; t++) {
            int idx = tid + t * 256;          // 1024 float4 slots
            int row = idx >> 3;               // 8 float4 per row (32 floats)
            int col = (idx & 7) << 2;
            float4 a4 = *(const float4*)(Ab + (size_t)row * K + kt + col);
            *(float4*)&As[row][col] = make_float4(f2tf(a4.x), f2tf(a4.y), f2tf(a4.z), f2tf(a4.w));
            float4 b4 = *(const float4*)(Bb + (size_t)row * K + kt + col);
            *(float4*)&Bs[row][col] = make_float4(f2tf(b4.x), f2tf(b4.y), f2tf(b4.z), f2tf(b4.w));
        }
        __syncthreads();
#pragma unroll
        for (int ks = 0; ks < 4; ks++) {
            const int k0 = ks * 8;
            unsigned a[4][4], b[4][2];
#pragma unroll
            for (int mt = 0; mt < 4; mt++) {
                int row = m_base + mt * 16 + (lane >> 2);
                a[mt][0] = __float_as_uint(As[row][k0 + (lane & 3)]);
                a[mt][1] = __float_as_uint(As[row + 8][k0 + (lane & 3)]);
                a[mt][2] = __float_as_uint(As[row][k0 + 4 + (lane & 3)]);
                a[mt][3] = __float_as_uint(As[row + 8][k0 + 4 + (lane & 3)]);
            }
#pragma unroll
            for (int nt = 0; nt < 4; nt++) {
                int col = n_base + nt * 8 + (lane >> 2);
                b[nt][0] = __float_as_uint(Bs[col][k0 + (lane & 3)]);
                b[nt][1] = __float_as_uint(Bs[col][k0 + 4 + (lane & 3)]);
            }
#pragma unroll
            for (int mt = 0; mt < 4; mt++)
#pragma unroll
                for (int nt = 0; nt < 4; nt++)
                    mma_tf32(acc[mt][nt], a[mt], b[nt]);
        }
        __syncthreads();
    }

#pragma unroll
    for (int mt = 0; mt < 4; mt++) {
        int row0 = blockIdx.y * GBM + m_base + mt * 16 + (lane >> 2);
#pragma unroll
        for (int nt = 0; nt < 4; nt++) {
            int col = blockIdx.x * GBN + n_base + nt * 8 + 2 * (lane & 3);
            *(float2*)(C + (size_t)row0 * N + col)       = make_float2(acc[mt][nt][0], acc[mt][nt][1]);
            *(float2*)(C + (size_t)(row0 + 8) * N + col) = make_float2(acc[mt][nt][2], acc[mt][nt][3]);
        }
    }
}

// ---------------------------------------------------------------------------
// RMSNorm + RoPE (unchanged)
// ---------------------------------------------------------------------------
__global__ void rmsnorm_rope_kernel(float* __restrict__ buf, int rowStride,
                                    const float* __restrict__ w,
                                    const float* __restrict__ cosp,
                                    const float* __restrict__ sinp) {
    const int s = blockIdx.x, h = blockIdx.y, d = threadIdx.x;
    float* p = buf + (size_t)s * rowStride + h * HD;
    float v = p[d];
    float sq = v * v;
#pragma unroll
    for (int off = 16; off > 0; off >>= 1)
        sq += __shfl_xor_sync(0xffffffffu, sq, off);
    __shared__ float red[4];
    __shared__ float xs[HD];
    if ((d & 31) == 0) red[d >> 5] = sq;
    __syncthreads();
    float sum = red[0] + red[1] + red[2] + red[3];
    float r = rsqrtf(sum * (1.0f / HD) + 1e-6f);
    float xn = v * r * w[d];
    xs[d] = xn;
    __syncthreads();
    float rot = (d < 64) ? -xs[d + 64] : xs[d - 64];
    p[d] = xn * cosp[(size_t)s * HD + d] + rot * sinp[(size_t)s * HD + d];
}

// ---------------------------------------------------------------------------
// Flash attention on tf32 mma. 64x64 tiles, 128 threads (4 warps),
// each warp owns 16 query rows. P routed through smem.
// Strides: sQ/sK 132 (4 mod 32), sV 136 (8 mod 32), sP 68 -> conflict-free.
// ---------------------------------------------------------------------------
#define FST 132
#define VST 136
#define PST 68

__global__ __launch_bounds__(128)
void flash_tf32(const float* __restrict__ Q, const float* __restrict__ K,
                const float* __restrict__ V, float* __restrict__ O) {
    extern __shared__ float sm[];
    float* sQ  = sm;                 // 64 * 132
    float* sKV = sm + 64 * FST;      // 64 * 136 (K uses stride FST, V uses VST)
    float* sP  = sKV + 64 * VST;     // 64 * 68

    const int tid = threadIdx.x, lane = tid & 31, warp = tid >> 5;
    const int mt = blockIdx.x, h = blockIdx.y;
    const int kvh = h >> 2;
    const int m0 = mt * 64;
    const int r0 = warp * 16 + (lane >> 2);   // local q row (and +8)

    // Load Q tile 64x128 (tf32-rounded)
#pragma unroll
    for (int t = 0; t < 16; t++) {
        int idx = tid + t * 128;
        int row = idx >> 5;
        int col = (idx & 31) << 2;
        float4 q4 = *(const float4*)(Q + (size_t)(m0 + row) * DIM + h * HD + col);
        *(float4*)&sQ[row * FST + col] = make_float4(f2tf(q4.x), f2tf(q4.y), f2tf(q4.z), f2tf(q4.w));
    }

    float o[16][4];
    float mi[2] = {-1e30f, -1e30f}, li[2] = {0.f, 0.f};
#pragma unroll
    for (int i = 0; i < 16; i++)
#pragma unroll
        for (int j = 0; j < 4; j++) o[i][j] = 0.f;

    const float sc = 0.08838834764831845f;

    for (int nt = 0; nt <= mt; nt++) {
        const int n0 = nt * 64;
        // K tile
#pragma unroll
        for (int t = 0; t < 16; t++) {
            int idx = tid + t * 128;
            int row = idx >> 5;
            int col = (idx & 31) << 2;
            float4 k4 = *(const float4*)(K + (size_t)(n0 + row) * KV_DIM + kvh * HD + col);
            *(float4*)&sKV[row * FST + col] = make_float4(f2tf(k4.x), f2tf(k4.y), f2tf(k4.z), f2tf(k4.w));
        }
        __syncthreads();

        // S = Q K^T : 8 n-tiles x 16 k-chunks
        float s[8][4];
#pragma unroll
        for (int i = 0; i < 8; i++)
#pragma unroll
            for (int j = 0; j < 4; j++) s[i][j] = 0.f;

#pragma unroll
        for (int kc = 0; kc < 16; kc++) {
            const int k0 = kc * 8;
            unsigned a[4];
            a[0] = __float_as_uint(sQ[r0 * FST + k0 + (lane & 3)]);
            a[1] = __float_as_uint(sQ[(r0 + 8) * FST + k0 + (lane & 3)]);
            a[2] = __float_as_uint(sQ[r0 * FST + k0 + 4 + (lane & 3)]);
            a[3] = __float_as_uint(sQ[(r0 + 8) * FST + k0 + 4 + (lane & 3)]);
#pragma unroll
            for (int n8 = 0; n8 < 8; n8++) {
                unsigned b[2];
                int nr = n8 * 8 + (lane >> 2);
                b[0] = __float_as_uint(sKV[nr * FST + k0 + (lane & 3)]);
                b[1] = __float_as_uint(sKV[nr * FST + k0 + 4 + (lane & 3)]);
                mma_tf32(s[n8], a, b);
            }
        }

        // scale + causal mask
        const int gr0 = m0 + r0, gr1 = gr0 + 8;
#pragma unroll
        for (int n8 = 0; n8 < 8; n8++) {
            int gc = n0 + n8 * 8 + 2 * (lane & 3);
            s[n8][0] *= sc; s[n8][1] *= sc; s[n8][2] *= sc; s[n8][3] *= sc;
            if (nt == mt) {
                if (gc     > gr0) s[n8][0] = -1e30f;
                if (gc + 1 > gr0) s[n8][1] = -1e30f;
                if (gc     > gr1) s[n8][2] = -1e30f;
                if (gc + 1 > gr1) s[n8][3] = -1e30f;
            }
        }

        // online softmax, rows r0 (regs 0,1) and r0+8 (regs 2,3)
#pragma unroll
        for (int rr = 0; rr < 2; rr++) {
            float mloc = -1e30f;
#pragma unroll
            for (int n8 = 0; n8 < 8; n8++)
                mloc = fmaxf(mloc, fmaxf(s[n8][2 * rr], s[n8][2 * rr + 1]));
            mloc = fmaxf(mloc, __shfl_xor_sync(0xffffffffu, mloc, 1));
            mloc = fmaxf(mloc, __shfl_xor_sync(0xffffffffu, mloc, 2));
            float mnew = fmaxf(mi[rr], mloc);
            float corr = __expf(mi[rr] - mnew);
            float rs = 0.f;
#pragma unroll
            for (int n8 = 0; n8 < 8; n8++) {
                float p0 = __expf(s[n8][2 * rr] - mnew);
                float p1 = __expf(s[n8][2 * rr + 1] - mnew);
                s[n8][2 * rr] = p0; s[n8][2 * rr + 1] = p1;
                rs += p0 + p1;
            }
            rs += __shfl_xor_sync(0xffffffffu, rs, 1);
            rs += __shfl_xor_sync(0xffffffffu, rs, 2);
            li[rr] = li[rr] * corr + rs;
            mi[rr] = mnew;
#pragma unroll
            for (int i = 0; i < 16; i++) {
                o[i][2 * rr]     *= corr;
                o[i][2 * rr + 1] *= corr;
            }
            // store P (tf32-rounded)
            int prow = (rr == 0) ? r0 : r0 + 8;
#pragma unroll
            for (int n8 = 0; n8 < 8; n8++) {
                int pc = n8 * 8 + 2 * (lane & 3);
                sP[prow * PST + pc]     = f2tf(s[n8][2 * rr]);
                sP[prow * PST + pc + 1] = f2tf(s[n8][2 * rr + 1]);
            }
        }
        __syncthreads();   // all warps done reading sKV (K)

        // V tile (stride VST)
#pragma unroll
        for (int t = 0; t < 16; t++) {
            int idx = tid + t * 128;
            int row = idx >> 5;
            int col = (idx & 31) << 2;
            float4 v4 = *(const float4*)(V + (size_t)(n0 + row) * KV_DIM + kvh * HD + col);
            *(float4*)&sKV[row * VST + col] = make_float4(f2tf(v4.x), f2tf(v4.y), f2tf(v4.z), f2tf(v4.w));
        }
        __syncthreads();

        // O += P @ V : 8 k-chunks x 16 n-tiles
#pragma unroll
        for (int kc = 0; kc < 8; kc++) {
            const int k0 = kc * 8;
            unsigned a[4];
            a[0] = __float_as_uint(sP[r0 * PST + k0 + (lane & 3)]);
            a[1] = __float_as_uint(sP[(r0 + 8) * PST + k0 + (lane & 3)]);
            a[2] = __float_as_uint(sP[r0 * PST + k0 + 4 + (lane & 3)]);
            a[3] = __float_as_uint(sP[(r0 + 8) * PST + k0 + 4 + (lane & 3)]);
#pragma unroll
            for (int n16 = 0; n16 < 16; n16++) {
                unsigned b[2];
                int nc = n16 * 8 + (lane >> 2);
                b[0] = __float_as_uint(sKV[(k0 + (lane & 3)) * VST + nc]);
                b[1] = __float_as_uint(sKV[(k0 + 4 + (lane & 3)) * VST + nc]);
                mma_tf32(o[n16], a, b);
            }
        }
        __syncthreads();   // before next iter overwrites sKV with K
    }

    // epilogue
    float inv0 = 1.f / li[0], inv1 = 1.f / li[1];
#pragma unroll
    for (int n16 = 0; n16 < 16; n16++) {
        int gc = n16 * 8 + 2 * (lane & 3);
        float* op0 = O + (size_t)(m0 + r0) * DIM + h * HD + gc;
        float* op1 = O + (size_t)(m0 + r0 + 8) * DIM + h * HD + gc;
        *(float2*)op0 = make_float2(o[n16][0] * inv0, o[n16][1] * inv0);
        *(float2*)op1 = make_float2(o[n16][2] * inv1, o[n16][3] * inv1);
    }
}

// ---------------------------------------------------------------------------
extern "C" void kernel_launch(void* const* d_in, const int* in_sizes, int n_in,
                              void* d_out, int out_size) {
    const float* x    = (const float*)d_in[0];
    const float* cosp = (const float*)d_in[1];
    const float* sinp = (const float*)d_in[2];
    const float* wq   = (const float*)d_in[3];
    const float* wk   = (const float*)d_in[4];
    const float* wv   = (const float*)d_in[5];
    const float* wo   = (const float*)d_in[6];
    const float* qw   = (const float*)d_in[7];
    const float* kw   = (const float*)d_in[8];
    float* out = (float*)d_out;

    float *q, *k, *v, *attn;
    cudaGetSymbolAddress((void**)&q, g_q);
    cudaGetSymbolAddress((void**)&k, g_k);
    cudaGetSymbolAddress((void**)&v, g_v);
    cudaGetSymbolAddress((void**)&attn, g_attn);

    const int flash_smem = (64 * FST + 64 * VST + 64 * PST) * (int)sizeof(float);
    cudaFuncSetAttribute(flash_tf32, cudaFuncAttributeMaxDynamicSharedMemorySize, flash_smem);

    gemm_tf32_nt<<<dim3(DIM / GBN, S_LEN / GBM), 256>>>(x, wq, q, S_LEN, DIM, DIM);
    gemm_tf32_nt<<<dim3(KV_DIM / GBN, S_LEN / GBM), 256>>>(x, wk, k, S_LEN, KV_DIM, DIM);
    gemm_tf32_nt<<<dim3(KV_DIM / GBN, S_LEN / GBM), 256>>>(x, wv, v, S_LEN, KV_DIM, DIM);

    rmsnorm_rope_kernel<<<dim3(S_LEN, NH), HD>>>(q, DIM, qw, cosp, sinp);
    rmsnorm_rope_kernel<<<dim3(S_LEN, NKV), HD>>>(k, KV_DIM, kw, cosp, sinp);

    flash_tf32<<<dim3(S_LEN / 64, NH), 128, flash_smem>>>(q, k, v, attn);

    gemm_tf32_nt<<<dim3(DIM / GBN, S_LEN / GBM), 256>>>(attn, wo, out, S_LEN, DIM, DIM);
}

// round 4
// speedup vs baseline: 5.8271x; 2.0204x over previous
#include <cuda_runtime.h>
#include <cuda_fp16.h>
#include <math.h>

#define S_LEN 2048
#define DIM 4096
#define NH 32
#define NKV 8
#define HD 128
#define KV_DIM 1024

// f16 scratch (allocation-free rule: __device__ globals)
__device__ __half g_xh[S_LEN * DIM];
__device__ __half g_wqh[DIM * DIM];
__device__ __half g_wkh[KV_DIM * DIM];
__device__ __half g_wvh[KV_DIM * DIM];
__device__ __half g_woh[DIM * DIM];
__device__ __half g_q[S_LEN * DIM];
__device__ __half g_k[S_LEN * KV_DIM];
__device__ __half g_v[S_LEN * KV_DIM];
__device__ __half g_attn[S_LEN * DIM];

// ---------------------------------------------------------------------------
// helpers
// ---------------------------------------------------------------------------
__device__ __forceinline__ unsigned smem_u32(const void* p) {
    unsigned a;
    asm("{ .reg .u64 t; cvta.to.shared.u64 t, %1; cvt.u32.u64 %0, t; }" : "=r"(a) : "l"(p));
    return a;
}

__device__ __forceinline__ void mma_f16(float c[4], const unsigned a[4], const unsigned b[2]) {
    asm volatile(
        "mma.sync.aligned.m16n8k16.row.col.f32.f16.f16.f32 "
        "{%0,%1,%2,%3},{%4,%5,%6,%7},{%8,%9},{%0,%1,%2,%3};"
        : "+f"(c[0]), "+f"(c[1]), "+f"(c[2]), "+f"(c[3])
        : "r"(a[0]), "r"(a[1]), "r"(a[2]), "r"(a[3]), "r"(b[0]), "r"(b[1]));
}

__device__ __forceinline__ void ldsm4(unsigned r[4], unsigned addr) {
    asm volatile("ldmatrix.sync.aligned.m8n8.x4.shared.b16 {%0,%1,%2,%3}, [%4];"
                 : "=r"(r[0]), "=r"(r[1]), "=r"(r[2]), "=r"(r[3]) : "r"(addr));
}

__device__ __forceinline__ void ldsm4t(unsigned r[4], unsigned addr) {
    asm volatile("ldmatrix.sync.aligned.m8n8.x4.trans.shared.b16 {%0,%1,%2,%3}, [%4];"
                 : "=r"(r[0]), "=r"(r[1]), "=r"(r[2]), "=r"(r[3]) : "r"(addr));
}

__device__ __forceinline__ void cpa16(unsigned dst, const void* src) {
    asm volatile("cp.async.cg.shared.global [%0], [%1], 16;" :: "r"(dst), "l"(src));
}

// ---------------------------------------------------------------------------
// fp32 -> fp16 conversion
// ---------------------------------------------------------------------------
__global__ void cvt_f16(const float* __restrict__ s, __half* __restrict__ d, int n4) {
    int i = blockIdx.x * 256 + threadIdx.x;
    if (i >= n4) return;
    float4 v = ((const float4*)s)[i];
    ((__half2*)d)[2 * i]     = __floats2half2_rn(v.x, v.y);
    ((__half2*)d)[2 * i + 1] = __floats2half2_rn(v.z, v.w);
}

// ---------------------------------------------------------------------------
// fp16 GEMM: C[M,N] = A[M,K] @ B[N,K]^T  (A,B f16 row-major k-contiguous)
// CTA 128x128, K-step 32, 3-stage cp.async, 8 warps (2m x 4n), warp 64x32.
// Up to 3 output partitions along N (for fused QKV). out_f32 selects epilogue.
// ---------------------------------------------------------------------------
#define AST 40                         // smem row stride (halfs), 32 + 8 pad
#define STAGE_H (128 * AST)            // halfs per operand per stage
#define STAGE_BYTES (2 * STAGE_H * 2)  // A + B per stage = 20480 B
#define GSMEM (3 * STAGE_BYTES)

__device__ __forceinline__ void g_load_stage(unsigned sbuf, const __half* Ap,
                                             const __half* Bp, int kt, int K, int tid) {
#pragma unroll
    for (int t = 0; t < 2; t++) {
        int idx = tid + t * 256;          // 512 chunks of 16B each
        int row = idx >> 2, ch = idx & 3;
        cpa16(sbuf + (row * AST + ch * 8) * 2, Ap + (size_t)row * K + kt + ch * 8);
        cpa16(sbuf + (STAGE_H + row * AST + ch * 8) * 2, Bp + (size_t)row * K + kt + ch * 8);
    }
}

__global__ __launch_bounds__(256, 2)
void gemm_f16(const __half* __restrict__ Ah,
              const __half* __restrict__ B0, const __half* __restrict__ B1,
              const __half* __restrict__ B2,
              void* C0, void* C1, void* C2,
              int ldc0, int ldc1, int ldc2,
              int n1, int n2, int K, int out_f32) {
    extern __shared__ __align__(16) char smem[];
    const unsigned sbase = smem_u32(smem);
    const int tid = threadIdx.x, lane = tid & 31, warp = tid >> 5;
    const int mbase = (warp >> 2) * 64, nbase = (warp & 3) * 32;
    const int m0 = blockIdx.y * 128;
    const int nt = blockIdx.x;

    const __half* Bsel; void* Csel; int ldc, ncol0;
    if (nt < n1)      { Bsel = B0 + (size_t)nt * 128 * K;        Csel = C0; ldc = ldc0; ncol0 = nt * 128; }
    else if (nt < n2) { Bsel = B1 + (size_t)(nt - n1) * 128 * K; Csel = C1; ldc = ldc1; ncol0 = (nt - n1) * 128; }
    else              { Bsel = B2 + (size_t)(nt - n2) * 128 * K; Csel = C2; ldc = ldc2; ncol0 = (nt - n2) * 128; }
    const __half* Ap = Ah + (size_t)m0 * K;

    float acc[4][4][4];
#pragma unroll
    for (int i = 0; i < 4; i++)
#pragma unroll
        for (int j = 0; j < 4; j++)
#pragma unroll
            for (int r = 0; r < 4; r++) acc[i][j][r] = 0.f;

    const int NS = K / 32;
    // prologue: stages 0,1
    g_load_stage(sbase, Ap, Bsel, 0, K, tid);
    asm volatile("cp.async.commit_group;" ::: "memory");
    g_load_stage(sbase + STAGE_BYTES, Ap, Bsel, 32, K, tid);
    asm volatile("cp.async.commit_group;" ::: "memory");

    for (int s = 0; s < NS; s++) {
        if (s <= NS - 2) asm volatile("cp.async.wait_group 1;" ::: "memory");
        else             asm volatile("cp.async.wait_group 0;" ::: "memory");
        __syncthreads();
        if (s + 2 < NS) {
            g_load_stage(sbase + ((s + 2) % 3) * STAGE_BYTES, Ap, Bsel, (s + 2) * 32, K, tid);
            asm volatile("cp.async.commit_group;" ::: "memory");
        }
        const unsigned sA = sbase + (s % 3) * STAGE_BYTES;
        const unsigned sB = sA + STAGE_H * 2;
#pragma unroll
        for (int kc = 0; kc < 32; kc += 16) {
            unsigned a[4][4], b[4][2];
#pragma unroll
            for (int mt = 0; mt < 4; mt++)
                ldsm4(a[mt], sA + ((mbase + mt * 16 + (lane & 15)) * AST + kc + (lane >> 4) * 8) * 2);
#pragma unroll
            for (int p = 0; p < 2; p++) {
                unsigned t4[4];
                ldsm4(t4, sB + ((nbase + p * 16 + (lane & 15)) * AST + kc + (lane >> 4) * 8) * 2);
                b[2 * p][0] = t4[0]; b[2 * p][1] = t4[2];
                b[2 * p + 1][0] = t4[1]; b[2 * p + 1][1] = t4[3];
            }
#pragma unroll
            for (int mt = 0; mt < 4; mt++)
#pragma unroll
                for (int n4 = 0; n4 < 4; n4++)
                    mma_f16(acc[mt][n4], a[mt], b[n4]);
        }
        __syncthreads();
    }

    // epilogue
#pragma unroll
    for (int mt = 0; mt < 4; mt++) {
        int row0 = m0 + mbase + mt * 16 + (lane >> 2);
#pragma unroll
        for (int n4 = 0; n4 < 4; n4++) {
            int col = ncol0 + nbase + n4 * 8 + 2 * (lane & 3);
            if (out_f32) {
                float* Cp = (float*)Csel;
                *(float2*)(Cp + (size_t)row0 * ldc + col)       = make_float2(acc[mt][n4][0], acc[mt][n4][1]);
                *(float2*)(Cp + (size_t)(row0 + 8) * ldc + col) = make_float2(acc[mt][n4][2], acc[mt][n4][3]);
            } else {
                __half* Cp = (__half*)Csel;
                *(__half2*)(Cp + (size_t)row0 * ldc + col)       = __floats2half2_rn(acc[mt][n4][0], acc[mt][n4][1]);
                *(__half2*)(Cp + (size_t)(row0 + 8) * ldc + col) = __floats2half2_rn(acc[mt][n4][2], acc[mt][n4][3]);
            }
        }
    }
}

// ---------------------------------------------------------------------------
// RMSNorm + RoPE, f16 in/out, f32 math. grid = (S, nheads), 128 threads.
// ---------------------------------------------------------------------------
__global__ void rmsnorm_rope_kernel(__half* __restrict__ buf, int rowStride,
                                    const float* __restrict__ w,
                                    const float* __restrict__ cosp,
                                    const float* __restrict__ sinp) {
    const int s = blockIdx.x, h = blockIdx.y, d = threadIdx.x;
    __half* p = buf + (size_t)s * rowStride + h * HD;
    float v = __half2float(p[d]);
    float sq = v * v;
#pragma unroll
    for (int off = 16; off > 0; off >>= 1)
        sq += __shfl_xor_sync(0xffffffffu, sq, off);
    __shared__ float red[4];
    __shared__ float xs[HD];
    if ((d & 31) == 0) red[d >> 5] = sq;
    __syncthreads();
    float sum = red[0] + red[1] + red[2] + red[3];
    float r = rsqrtf(sum * (1.0f / HD) + 1e-6f);
    float xn = v * r * w[d];
    xs[d] = xn;
    __syncthreads();
    float rot = (d < 64) ? -xs[d + 64] : xs[d - 64];
    p[d] = __float2half_rn(xn * cosp[(size_t)s * HD + d] + rot * sinp[(size_t)s * HD + d]);
}

// ---------------------------------------------------------------------------
// Flash attention, fp16 mma. 64x64 tiles, 128 threads (4 warps),
// each warp 16 query rows. ldmatrix frags; V via ldmatrix.trans.
// smem (halfs): sQ 64x136 | sKV 64x136 (K then V) | sP 64x72.
// ---------------------------------------------------------------------------
#define FQS 136
#define FPS 72
#define FLASH_SMEM ((64 * FQS + 64 * FQS + 64 * FPS) * 2)

__global__ __launch_bounds__(128)
void flash_f16(const __half* __restrict__ Q, const __half* __restrict__ K,
               const __half* __restrict__ V, __half* __restrict__ O) {
    extern __shared__ __align__(16) char fsm[];
    __half* sQ  = (__half*)fsm;
    __half* sKV = sQ + 64 * FQS;
    __half* sP  = sKV + 64 * FQS;
    const unsigned uQ = smem_u32(sQ), uKV = smem_u32(sKV), uP = smem_u32(sP);

    const int tid = threadIdx.x, lane = tid & 31, warp = tid >> 5;
    const int mt = (gridDim.x - 1) - blockIdx.x;     // longest-first
    const int h = blockIdx.y;
    const int kvh = h >> 2;
    const int m0 = mt * 64;

    // Q tile 64x128 f16 (16B chunks)
#pragma unroll
    for (int t = 0; t < 8; t++) {
        int idx = tid + t * 128;
        int row = idx >> 4, ch = idx & 15;
        uint4 q4 = *(const uint4*)(Q + (size_t)(m0 + row) * DIM + h * HD + ch * 8);
        *(uint4*)(sQ + row * FQS + ch * 8) = q4;
    }

    float o[16][4];
    float mi[2] = {-1e30f, -1e30f}, li[2] = {0.f, 0.f};
#pragma unroll
    for (int i = 0; i < 16; i++)
#pragma unroll
        for (int j = 0; j < 4; j++) o[i][j] = 0.f;

    const float sc = 0.08838834764831845f;

    for (int nt = 0; nt <= mt; nt++) {
        const int n0 = nt * 64;
        // K tile
#pragma unroll
        for (int t = 0; t < 8; t++) {
            int idx = tid + t * 128;
            int row = idx >> 4, ch = idx & 15;
            uint4 k4 = *(const uint4*)(K + (size_t)(n0 + row) * KV_DIM + kvh * HD + ch * 8);
            *(uint4*)(sKV + row * FQS + ch * 8) = k4;
        }
        __syncthreads();

        // S = Q K^T
        float s[8][4];
#pragma unroll
        for (int i = 0; i < 8; i++)
#pragma unroll
            for (int j = 0; j < 4; j++) s[i][j] = 0.f;

#pragma unroll
        for (int kc = 0; kc < 8; kc++) {
            unsigned a[4], b[8][2];
            ldsm4(a, uQ + ((warp * 16 + (lane & 15)) * FQS + kc * 16 + (lane >> 4) * 8) * 2);
#pragma unroll
            for (int p = 0; p < 4; p++) {
                unsigned t4[4];
                ldsm4(t4, uKV + ((p * 16 + (lane & 15)) * FQS + kc * 16 + (lane >> 4) * 8) * 2);
                b[2 * p][0] = t4[0]; b[2 * p][1] = t4[2];
                b[2 * p + 1][0] = t4[1]; b[2 * p + 1][1] = t4[3];
            }
#pragma unroll
            for (int n8 = 0; n8 < 8; n8++)
                mma_f16(s[n8], a, b[n8]);
        }

        // scale + causal mask
        const int gr0 = m0 + warp * 16 + (lane >> 2), gr1 = gr0 + 8;
#pragma unroll
        for (int n8 = 0; n8 < 8; n8++) {
            int gc = n0 + n8 * 8 + 2 * (lane & 3);
            s[n8][0] *= sc; s[n8][1] *= sc; s[n8][2] *= sc; s[n8][3] *= sc;
            if (nt == mt) {
                if (gc     > gr0) s[n8][0] = -1e30f;
                if (gc + 1 > gr0) s[n8][1] = -1e30f;
                if (gc     > gr1) s[n8][2] = -1e30f;
                if (gc + 1 > gr1) s[n8][3] = -1e30f;
            }
        }

        // online softmax (rows lane>>2 and +8; 4 lanes/row -> xor 1,2)
#pragma unroll
        for (int rr = 0; rr < 2; rr++) {
            float mloc = -1e30f;
#pragma unroll
            for (int n8 = 0; n8 < 8; n8++)
                mloc = fmaxf(mloc, fmaxf(s[n8][2 * rr], s[n8][2 * rr + 1]));
            mloc = fmaxf(mloc, __shfl_xor_sync(0xffffffffu, mloc, 1));
            mloc = fmaxf(mloc, __shfl_xor_sync(0xffffffffu, mloc, 2));
            float mnew = fmaxf(mi[rr], mloc);
            float corr = __expf(mi[rr] - mnew);
            float rs = 0.f;
#pragma unroll
            for (int n8 = 0; n8 < 8; n8++) {
                float p0 = __expf(s[n8][2 * rr] - mnew);
                float p1 = __expf(s[n8][2 * rr + 1] - mnew);
                s[n8][2 * rr] = p0; s[n8][2 * rr + 1] = p1;
                rs += p0 + p1;
            }
            rs += __shfl_xor_sync(0xffffffffu, rs, 1);
            rs += __shfl_xor_sync(0xffffffffu, rs, 2);
            li[rr] = li[rr] * corr + rs;
            mi[rr] = mnew;
#pragma unroll
            for (int i = 0; i < 16; i++) {
                o[i][2 * rr]     *= corr;
                o[i][2 * rr + 1] *= corr;
            }
            int prow = warp * 16 + (lane >> 2) + rr * 8;
#pragma unroll
            for (int n8 = 0; n8 < 8; n8++) {
                int pc = n8 * 8 + 2 * (lane & 3);
                *(__half2*)(sP + prow * FPS + pc) =
                    __floats2half2_rn(s[n8][2 * rr], s[n8][2 * rr + 1]);
            }
        }
        __syncthreads();   // done reading K

        // V tile into same buffer
#pragma unroll
        for (int t = 0; t < 8; t++) {
            int idx = tid + t * 128;
            int row = idx >> 4, ch = idx & 15;
            uint4 v4 = *(const uint4*)(V + (size_t)(n0 + row) * KV_DIM + kvh * HD + ch * 8);
            *(uint4*)(sKV + row * FQS + ch * 8) = v4;
        }
        __syncthreads();

        // O += P @ V  (V^T frags via ldmatrix.trans)
#pragma unroll
        for (int kc = 0; kc < 4; kc++) {
            unsigned a[4];
            ldsm4(a, uP + ((warp * 16 + (lane & 15)) * FPS + kc * 16 + (lane >> 4) * 8) * 2);
#pragma unroll
            for (int p = 0; p < 8; p++) {
                unsigned t4[4];
                ldsm4t(t4, uKV + ((kc * 16 + ((lane >> 3) & 1) * 8 + (lane & 7)) * FQS
                                  + p * 16 + (lane >> 4) * 8) * 2);
                unsigned b0[2] = {t4[0], t4[1]};
                unsigned b1[2] = {t4[2], t4[3]};
                mma_f16(o[2 * p], a, b0);
                mma_f16(o[2 * p + 1], a, b1);
            }
        }
        __syncthreads();   // before next K overwrites sKV
    }

    // epilogue
    float inv0 = 1.f / li[0], inv1 = 1.f / li[1];
    const int row0 = m0 + warp * 16 + (lane >> 2);
#pragma unroll
    for (int n16 = 0; n16 < 16; n16++) {
        int gc = n16 * 8 + 2 * (lane & 3);
        *(__half2*)(O + (size_t)row0 * DIM + h * HD + gc) =
            __floats2half2_rn(o[n16][0] * inv0, o[n16][1] * inv0);
        *(__half2*)(O + (size_t)(row0 + 8) * DIM + h * HD + gc) =
            __floats2half2_rn(o[n16][2] * inv1, o[n16][3] * inv1);
    }
}

// ---------------------------------------------------------------------------
extern "C" void kernel_launch(void* const* d_in, const int* in_sizes, int n_in,
                              void* d_out, int out_size) {
    const float* x    = (const float*)d_in[0];
    const float* cosp = (const float*)d_in[1];
    const float* sinp = (const float*)d_in[2];
    const float* wq   = (const float*)d_in[3];
    const float* wk   = (const float*)d_in[4];
    const float* wv   = (const float*)d_in[5];
    const float* wo   = (const float*)d_in[6];
    const float* qw   = (const float*)d_in[7];
    const float* kw   = (const float*)d_in[8];
    float* out = (float*)d_out;

    __half *xh, *wqh, *wkh, *wvh, *woh, *q, *k, *v, *attn;
    cudaGetSymbolAddress((void**)&xh, g_xh);
    cudaGetSymbolAddress((void**)&wqh, g_wqh);
    cudaGetSymbolAddress((void**)&wkh, g_wkh);
    cudaGetSymbolAddress((void**)&wvh, g_wvh);
    cudaGetSymbolAddress((void**)&woh, g_woh);
    cudaGetSymbolAddress((void**)&q, g_q);
    cudaGetSymbolAddress((void**)&k, g_k);
    cudaGetSymbolAddress((void**)&v, g_v);
    cudaGetSymbolAddress((void**)&attn, g_attn);

    cudaFuncSetAttribute(gemm_f16, cudaFuncAttributeMaxDynamicSharedMemorySize, GSMEM);
    cudaFuncSetAttribute(flash_f16, cudaFuncAttributeMaxDynamicSharedMemorySize, FLASH_SMEM);

    // fp32 -> fp16
    cvt_f16<<<(S_LEN * DIM / 4) / 256, 256>>>(x, xh, S_LEN * DIM / 4);
    cvt_f16<<<(DIM * DIM / 4) / 256, 256>>>(wq, wqh, DIM * DIM / 4);
    cvt_f16<<<(KV_DIM * DIM / 4) / 256, 256>>>(wk, wkh, KV_DIM * DIM / 4);
    cvt_f16<<<(KV_DIM * DIM / 4) / 256, 256>>>(wv, wvh, KV_DIM * DIM / 4);
    cvt_f16<<<(DIM * DIM / 4) / 256, 256>>>(wo, woh, DIM * DIM / 4);

    // fused QKV projection (48 n-tiles: 32 Q | 8 K | 8 V), f16 out
    gemm_f16<<<dim3(48, S_LEN / 128), 256, GSMEM>>>(
        xh, wqh, wkh, wvh, q, k, v, DIM, KV_DIM, KV_DIM, 32, 40, DIM, 0);

    rmsnorm_rope_kernel<<<dim3(S_LEN, NH), HD>>>(q, DIM, qw, cosp, sinp);
    rmsnorm_rope_kernel<<<dim3(S_LEN, NKV), HD>>>(k, KV_DIM, kw, cosp, sinp);

    flash_f16<<<dim3(S_LEN / 64, NH), 128, FLASH_SMEM>>>(q, k, v, attn);

    // output projection, f32 out
    gemm_f16<<<dim3(32, S_LEN / 128), 256, GSMEM>>>(
        attn, woh, woh, woh, out, out, out, DIM, DIM, DIM, 32, 40, DIM, 1);
}

// round 5
// speedup vs baseline: 5.8468x; 1.0034x over previous
#include <cuda_runtime.h>
#include <cuda_fp16.h>
#include <math.h>

#define S_LEN 2048
#define DIM 4096
#define NH 32
#define NKV 8
#define HD 128
#define KV_DIM 1024

// f16 scratch (allocation-free rule: __device__ globals)
__device__ __half g_xh[S_LEN * DIM];
__device__ __half g_wqh[DIM * DIM];
__device__ __half g_wkh[KV_DIM * DIM];
__device__ __half g_wvh[KV_DIM * DIM];
__device__ __half g_woh[DIM * DIM];
__device__ __half g_q[S_LEN * DIM];
__device__ __half g_k[S_LEN * KV_DIM];
__device__ __half g_v[S_LEN * KV_DIM];
__device__ __half g_attn[S_LEN * DIM];

// ---------------------------------------------------------------------------
// helpers
// ---------------------------------------------------------------------------
__device__ __forceinline__ unsigned smem_u32(const void* p) {
    unsigned a;
    asm("{ .reg .u64 t; cvta.to.shared.u64 t, %1; cvt.u32.u64 %0, t; }" : "=r"(a) : "l"(p));
    return a;
}

__device__ __forceinline__ void mma_f16(float c[4], const unsigned a[4], const unsigned b[2]) {
    asm volatile(
        "mma.sync.aligned.m16n8k16.row.col.f32.f16.f16.f32 "
        "{%0,%1,%2,%3},{%4,%5,%6,%7},{%8,%9},{%0,%1,%2,%3};"
        : "+f"(c[0]), "+f"(c[1]), "+f"(c[2]), "+f"(c[3])
        : "r"(a[0]), "r"(a[1]), "r"(a[2]), "r"(a[3]), "r"(b[0]), "r"(b[1]));
}

__device__ __forceinline__ void ldsm4(unsigned r[4], unsigned addr) {
    asm volatile("ldmatrix.sync.aligned.m8n8.x4.shared.b16 {%0,%1,%2,%3}, [%4];"
                 : "=r"(r[0]), "=r"(r[1]), "=r"(r[2]), "=r"(r[3]) : "r"(addr));
}

__device__ __forceinline__ void ldsm4t(unsigned r[4], unsigned addr) {
    asm volatile("ldmatrix.sync.aligned.m8n8.x4.trans.shared.b16 {%0,%1,%2,%3}, [%4];"
                 : "=r"(r[0]), "=r"(r[1]), "=r"(r[2]), "=r"(r[3]) : "r"(addr));
}

__device__ __forceinline__ void cpa16(unsigned dst, const void* src) {
    asm volatile("cp.async.cg.shared.global [%0], [%1], 16;" :: "r"(dst), "l"(src));
}

// ---------------------------------------------------------------------------
// fp32 -> fp16 conversion
// ---------------------------------------------------------------------------
__global__ void cvt_f16(const float* __restrict__ s, __half* __restrict__ d, int n4) {
    int i = blockIdx.x * 256 + threadIdx.x;
    if (i >= n4) return;
    float4 v = ((const float4*)s)[i];
    ((__half2*)d)[2 * i]     = __floats2half2_rn(v.x, v.y);
    ((__half2*)d)[2 * i + 1] = __floats2half2_rn(v.z, v.w);
}

// ---------------------------------------------------------------------------
// fp16 GEMM: C[M,N] = A[M,K] @ B[N,K]^T, CTA tile 128x256, K-step 32,
// 3-stage cp.async, 256 threads = 8 warps (2m x 4n), warp tile 64x64.
// Arithmetic intensity 2x vs 128x128 -> below LTS bandwidth cap.
// Up to 3 output partitions along N (fused QKV). out_f32 selects epilogue.
// ---------------------------------------------------------------------------
#define AST 40                              // smem row stride (halfs)
#define A_H (128 * AST)                     // A halfs per stage
#define B_H (256 * AST)                     // B halfs per stage
#define STAGE_BYTES ((A_H + B_H) * 2)       // 30720 B
#define GSMEM (3 * STAGE_BYTES)             // 92160 B

__device__ __forceinline__ void g_load_stage(unsigned sbuf, const __half* Ap,
                                             const __half* Bp, int kt, int K, int tid) {
#pragma unroll
    for (int t = 0; t < 2; t++) {           // A: 128 rows x 4 chunks
        int idx = tid + t * 256;
        int row = idx >> 2, ch = idx & 3;
        cpa16(sbuf + (row * AST + ch * 8) * 2, Ap + (size_t)row * K + kt + ch * 8);
    }
#pragma unroll
    for (int t = 0; t < 4; t++) {           // B: 256 rows x 4 chunks
        int idx = tid + t * 256;
        int row = idx >> 2, ch = idx & 3;
        cpa16(sbuf + (A_H + row * AST + ch * 8) * 2, Bp + (size_t)row * K + kt + ch * 8);
    }
}

__global__ __launch_bounds__(256, 1)
void gemm_f16(const __half* __restrict__ Ah,
              const __half* __restrict__ B0, const __half* __restrict__ B1,
              const __half* __restrict__ B2,
              void* C0, void* C1, void* C2,
              int ldc0, int ldc1, int ldc2,
              int n1, int n2, int K, int out_f32) {
    extern __shared__ __align__(16) char smem[];
    const unsigned sbase = smem_u32(smem);
    const int tid = threadIdx.x, lane = tid & 31, warp = tid >> 5;
    const int mbase = (warp >> 2) * 64, nbase = (warp & 3) * 64;
    const int m0 = blockIdx.y * 128;
    const int nt = blockIdx.x;              // 256-wide N tile index

    const __half* Bsel; void* Csel; int ldc, ncol0;
    if (nt < n1)      { Bsel = B0 + (size_t)nt * 256 * K;        Csel = C0; ldc = ldc0; ncol0 = nt * 256; }
    else if (nt < n2) { Bsel = B1 + (size_t)(nt - n1) * 256 * K; Csel = C1; ldc = ldc1; ncol0 = (nt - n1) * 256; }
    else              { Bsel = B2 + (size_t)(nt - n2) * 256 * K; Csel = C2; ldc = ldc2; ncol0 = (nt - n2) * 256; }
    const __half* Ap = Ah + (size_t)m0 * K;

    float acc[4][8][4];
#pragma unroll
    for (int i = 0; i < 4; i++)
#pragma unroll
        for (int j = 0; j < 8; j++)
#pragma unroll
            for (int r = 0; r < 4; r++) acc[i][j][r] = 0.f;

    const int NS = K / 32;
    g_load_stage(sbase, Ap, Bsel, 0, K, tid);
    asm volatile("cp.async.commit_group;" ::: "memory");
    g_load_stage(sbase + STAGE_BYTES, Ap, Bsel, 32, K, tid);
    asm volatile("cp.async.commit_group;" ::: "memory");

    for (int s = 0; s < NS; s++) {
        if (s <= NS - 2) asm volatile("cp.async.wait_group 1;" ::: "memory");
        else             asm volatile("cp.async.wait_group 0;" ::: "memory");
        __syncthreads();
        if (s + 2 < NS) {
            g_load_stage(sbase + ((s + 2) % 3) * STAGE_BYTES, Ap, Bsel, (s + 2) * 32, K, tid);
            asm volatile("cp.async.commit_group;" ::: "memory");
        }
        const unsigned sA = sbase + (s % 3) * STAGE_BYTES;
        const unsigned sB = sA + A_H * 2;
#pragma unroll
        for (int kc = 0; kc < 32; kc += 16) {
            unsigned a[4][4], b[8][2];
#pragma unroll
            for (int mt = 0; mt < 4; mt++)
                ldsm4(a[mt], sA + ((mbase + mt * 16 + (lane & 15)) * AST + kc + (lane >> 4) * 8) * 2);
#pragma unroll
            for (int p = 0; p < 4; p++) {
                unsigned t4[4];
                ldsm4(t4, sB + ((nbase + p * 16 + (lane & 15)) * AST + kc + (lane >> 4) * 8) * 2);
                b[2 * p][0] = t4[0]; b[2 * p][1] = t4[2];
                b[2 * p + 1][0] = t4[1]; b[2 * p + 1][1] = t4[3];
            }
#pragma unroll
            for (int mt = 0; mt < 4; mt++)
#pragma unroll
                for (int n8 = 0; n8 < 8; n8++)
                    mma_f16(acc[mt][n8], a[mt], b[n8]);
        }
        __syncthreads();
    }

    // epilogue
#pragma unroll
    for (int mt = 0; mt < 4; mt++) {
        int row0 = m0 + mbase + mt * 16 + (lane >> 2);
#pragma unroll
        for (int n8 = 0; n8 < 8; n8++) {
            int col = ncol0 + nbase + n8 * 8 + 2 * (lane & 3);
            if (out_f32) {
                float* Cp = (float*)Csel;
                *(float2*)(Cp + (size_t)row0 * ldc + col)       = make_float2(acc[mt][n8][0], acc[mt][n8][1]);
                *(float2*)(Cp + (size_t)(row0 + 8) * ldc + col) = make_float2(acc[mt][n8][2], acc[mt][n8][3]);
            } else {
                __half* Cp = (__half*)Csel;
                *(__half2*)(Cp + (size_t)row0 * ldc + col)       = __floats2half2_rn(acc[mt][n8][0], acc[mt][n8][1]);
                *(__half2*)(Cp + (size_t)(row0 + 8) * ldc + col) = __floats2half2_rn(acc[mt][n8][2], acc[mt][n8][3]);
            }
        }
    }
}

// ---------------------------------------------------------------------------
// RMSNorm + RoPE, f16 in/out, f32 math.
// ---------------------------------------------------------------------------
__global__ void rmsnorm_rope_kernel(__half* __restrict__ buf, int rowStride,
                                    const float* __restrict__ w,
                                    const float* __restrict__ cosp,
                                    const float* __restrict__ sinp) {
    const int s = blockIdx.x, h = blockIdx.y, d = threadIdx.x;
    __half* p = buf + (size_t)s * rowStride + h * HD;
    float v = __half2float(p[d]);
    float sq = v * v;
#pragma unroll
    for (int off = 16; off > 0; off >>= 1)
        sq += __shfl_xor_sync(0xffffffffu, sq, off);
    __shared__ float red[4];
    __shared__ float xs[HD];
    if ((d & 31) == 0) red[d >> 5] = sq;
    __syncthreads();
    float sum = red[0] + red[1] + red[2] + red[3];
    float r = rsqrtf(sum * (1.0f / HD) + 1e-6f);
    float xn = v * r * w[d];
    xs[d] = xn;
    __syncthreads();
    float rot = (d < 64) ? -xs[d + 64] : xs[d - 64];
    p[d] = __float2half_rn(xn * cosp[(size_t)s * HD + d] + rot * sinp[(size_t)s * HD + d]);
}

// ---------------------------------------------------------------------------
// Flash attention, fp16 mma (unchanged from R4).
// ---------------------------------------------------------------------------
#define FQS 136
#define FPS 72
#define FLASH_SMEM ((64 * FQS + 64 * FQS + 64 * FPS) * 2)

__global__ __launch_bounds__(128)
void flash_f16(const __half* __restrict__ Q, const __half* __restrict__ K,
               const __half* __restrict__ V, __half* __restrict__ O) {
    extern __shared__ __align__(16) char fsm[];
    __half* sQ  = (__half*)fsm;
    __half* sKV = sQ + 64 * FQS;
    __half* sP  = sKV + 64 * FQS;
    const unsigned uQ = smem_u32(sQ), uKV = smem_u32(sKV), uP = smem_u32(sP);

    const int tid = threadIdx.x, lane = tid & 31, warp = tid >> 5;
    const int mt = (gridDim.x - 1) - blockIdx.x;
    const int h = blockIdx.y;
    const int kvh = h >> 2;
    const int m0 = mt * 64;

#pragma unroll
    for (int t = 0; t < 8; t++) {
        int idx = tid + t * 128;
        int row = idx >> 4, ch = idx & 15;
        uint4 q4 = *(const uint4*)(Q + (size_t)(m0 + row) * DIM + h * HD + ch * 8);
        *(uint4*)(sQ + row * FQS + ch * 8) = q4;
    }

    float o[16][4];
    float mi[2] = {-1e30f, -1e30f}, li[2] = {0.f, 0.f};
#pragma unroll
    for (int i = 0; i < 16; i++)
#pragma unroll
        for (int j = 0; j < 4; j++) o[i][j] = 0.f;

    const float sc = 0.08838834764831845f;

    for (int nt = 0; nt <= mt; nt++) {
        const int n0 = nt * 64;
#pragma unroll
        for (int t = 0; t < 8; t++) {
            int idx = tid + t * 128;
            int row = idx >> 4, ch = idx & 15;
            uint4 k4 = *(const uint4*)(K + (size_t)(n0 + row) * KV_DIM + kvh * HD + ch * 8);
            *(uint4*)(sKV + row * FQS + ch * 8) = k4;
        }
        __syncthreads();

        float s[8][4];
#pragma unroll
        for (int i = 0; i < 8; i++)
#pragma unroll
            for (int j = 0; j < 4; j++) s[i][j] = 0.f;

#pragma unroll
        for (int kc = 0; kc < 8; kc++) {
            unsigned a[4], b[8][2];
            ldsm4(a, uQ + ((warp * 16 + (lane & 15)) * FQS + kc * 16 + (lane >> 4) * 8) * 2);
#pragma unroll
            for (int p = 0; p < 4; p++) {
                unsigned t4[4];
                ldsm4(t4, uKV + ((p * 16 + (lane & 15)) * FQS + kc * 16 + (lane >> 4) * 8) * 2);
                b[2 * p][0] = t4[0]; b[2 * p][1] = t4[2];
                b[2 * p + 1][0] = t4[1]; b[2 * p + 1][1] = t4[3];
            }
#pragma unroll
            for (int n8 = 0; n8 < 8; n8++)
                mma_f16(s[n8], a, b[n8]);
        }

        const int gr0 = m0 + warp * 16 + (lane >> 2), gr1 = gr0 + 8;
#pragma unroll
        for (int n8 = 0; n8 < 8; n8++) {
            int gc = n0 + n8 * 8 + 2 * (lane & 3);
            s[n8][0] *= sc; s[n8][1] *= sc; s[n8][2] *= sc; s[n8][3] *= sc;
            if (nt == mt) {
                if (gc     > gr0) s[n8][0] = -1e30f;
                if (gc + 1 > gr0) s[n8][1] = -1e30f;
                if (gc     > gr1) s[n8][2] = -1e30f;
                if (gc + 1 > gr1) s[n8][3] = -1e30f;
            }
        }

#pragma unroll
        for (int rr = 0; rr < 2; rr++) {
            float mloc = -1e30f;
#pragma unroll
            for (int n8 = 0; n8 < 8; n8++)
                mloc = fmaxf(mloc, fmaxf(s[n8][2 * rr], s[n8][2 * rr + 1]));
            mloc = fmaxf(mloc, __shfl_xor_sync(0xffffffffu, mloc, 1));
            mloc = fmaxf(mloc, __shfl_xor_sync(0xffffffffu, mloc, 2));
            float mnew = fmaxf(mi[rr], mloc);
            float corr = __expf(mi[rr] - mnew);
            float rs = 0.f;
#pragma unroll
            for (int n8 = 0; n8 < 8; n8++) {
                float p0 = __expf(s[n8][2 * rr] - mnew);
                float p1 = __expf(s[n8][2 * rr + 1] - mnew);
                s[n8][2 * rr] = p0; s[n8][2 * rr + 1] = p1;
                rs += p0 + p1;
            }
            rs += __shfl_xor_sync(0xffffffffu, rs, 1);
            rs += __shfl_xor_sync(0xffffffffu, rs, 2);
            li[rr] = li[rr] * corr + rs;
            mi[rr] = mnew;
#pragma unroll
            for (int i = 0; i < 16; i++) {
                o[i][2 * rr]     *= corr;
                o[i][2 * rr + 1] *= corr;
            }
            int prow = warp * 16 + (lane >> 2) + rr * 8;
#pragma unroll
            for (int n8 = 0; n8 < 8; n8++) {
                int pc = n8 * 8 + 2 * (lane & 3);
                *(__half2*)(sP + prow * FPS + pc) =
                    __floats2half2_rn(s[n8][2 * rr], s[n8][2 * rr + 1]);
            }
        }
        __syncthreads();

#pragma unroll
        for (int t = 0; t < 8; t++) {
            int idx = tid + t * 128;
            int row = idx >> 4, ch = idx & 15;
            uint4 v4 = *(const uint4*)(V + (size_t)(n0 + row) * KV_DIM + kvh * HD + ch * 8);
            *(uint4*)(sKV + row * FQS + ch * 8) = v4;
        }
        __syncthreads();

#pragma unroll
        for (int kc = 0; kc < 4; kc++) {
            unsigned a[4];
            ldsm4(a, uP + ((warp * 16 + (lane & 15)) * FPS + kc * 16 + (lane >> 4) * 8) * 2);
#pragma unroll
            for (int p = 0; p < 8; p++) {
                unsigned t4[4];
                ldsm4t(t4, uKV + ((kc * 16 + ((lane >> 3) & 1) * 8 + (lane & 7)) * FQS
                                  + p * 16 + (lane >> 4) * 8) * 2);
                unsigned b0[2] = {t4[0], t4[1]};
                unsigned b1[2] = {t4[2], t4[3]};
                mma_f16(o[2 * p], a, b0);
                mma_f16(o[2 * p + 1], a, b1);
            }
        }
        __syncthreads();
    }

    float inv0 = 1.f / li[0], inv1 = 1.f / li[1];
    const int row0 = m0 + warp * 16 + (lane >> 2);
#pragma unroll
    for (int n16 = 0; n16 < 16; n16++) {
        int gc = n16 * 8 + 2 * (lane & 3);
        *(__half2*)(O + (size_t)row0 * DIM + h * HD + gc) =
            __floats2half2_rn(o[n16][0] * inv0, o[n16][1] * inv0);
        *(__half2*)(O + (size_t)(row0 + 8) * DIM + h * HD + gc) =
            __floats2half2_rn(o[n16][2] * inv1, o[n16][3] * inv1);
    }
}

// ---------------------------------------------------------------------------
extern "C" void kernel_launch(void* const* d_in, const int* in_sizes, int n_in,
                              void* d_out, int out_size) {
    const float* x    = (const float*)d_in[0];
    const float* cosp = (const float*)d_in[1];
    const float* sinp = (const float*)d_in[2];
    const float* wq   = (const float*)d_in[3];
    const float* wk   = (const float*)d_in[4];
    const float* wv   = (const float*)d_in[5];
    const float* wo   = (const float*)d_in[6];
    const float* qw   = (const float*)d_in[7];
    const float* kw   = (const float*)d_in[8];
    float* out = (float*)d_out;

    __half *xh, *wqh, *wkh, *wvh, *woh, *q, *k, *v, *attn;
    cudaGetSymbolAddress((void**)&xh, g_xh);
    cudaGetSymbolAddress((void**)&wqh, g_wqh);
    cudaGetSymbolAddress((void**)&wkh, g_wkh);
    cudaGetSymbolAddress((void**)&wvh, g_wvh);
    cudaGetSymbolAddress((void**)&woh, g_woh);
    cudaGetSymbolAddress((void**)&q, g_q);
    cudaGetSymbolAddress((void**)&k, g_k);
    cudaGetSymbolAddress((void**)&v, g_v);
    cudaGetSymbolAddress((void**)&attn, g_attn);

    cudaFuncSetAttribute(gemm_f16, cudaFuncAttributeMaxDynamicSharedMemorySize, GSMEM);
    cudaFuncSetAttribute(flash_f16, cudaFuncAttributeMaxDynamicSharedMemorySize, FLASH_SMEM);

    // fp32 -> fp16
    cvt_f16<<<(S_LEN * DIM / 4) / 256, 256>>>(x, xh, S_LEN * DIM / 4);
    cvt_f16<<<(DIM * DIM / 4) / 256, 256>>>(wq, wqh, DIM * DIM / 4);
    cvt_f16<<<(KV_DIM * DIM / 4) / 256, 256>>>(wk, wkh, KV_DIM * DIM / 4);
    cvt_f16<<<(KV_DIM * DIM / 4) / 256, 256>>>(wv, wvh, KV_DIM * DIM / 4);
    cvt_f16<<<(DIM * DIM / 4) / 256, 256>>>(wo, woh, DIM * DIM / 4);

    // fused QKV projection: 24 N-tiles of 256 (16 Q | 4 K | 4 V), f16 out
    gemm_f16<<<dim3(24, S_LEN / 128), 256, GSMEM>>>(
        xh, wqh, wkh, wvh, q, k, v, DIM, KV_DIM, KV_DIM, 16, 20, DIM, 0);

    rmsnorm_rope_kernel<<<dim3(S_LEN, NH), HD>>>(q, DIM, qw, cosp, sinp);
    rmsnorm_rope_kernel<<<dim3(S_LEN, NKV), HD>>>(k, KV_DIM, kw, cosp, sinp);

    flash_f16<<<dim3(S_LEN / 64, NH), 128, FLASH_SMEM>>>(q, k, v, attn);

    // output projection: 16 N-tiles of 256, f32 out
    gemm_f16<<<dim3(16, S_LEN / 128), 256, GSMEM>>>(
        attn, woh, woh, woh, out, out, out, DIM, DIM, DIM, 16, 20, DIM, 1);
}

// round 6
// speedup vs baseline: 5.8627x; 1.0027x over previous
#include <cuda_runtime.h>
#include <cuda_fp16.h>
#include <math.h>

#define S_LEN 2048
#define DIM 4096
#define NH 32
#define NKV 8
#define HD 128
#define KV_DIM 1024

// f16 scratch (allocation-free rule: __device__ globals)
__device__ __half g_xh[S_LEN * DIM];
__device__ __half g_wqh[DIM * DIM];
__device__ __half g_wkh[KV_DIM * DIM];
__device__ __half g_wvh[KV_DIM * DIM];
__device__ __half g_woh[DIM * DIM];
__device__ __half g_q[S_LEN * DIM];
__device__ __half g_k[S_LEN * KV_DIM];
__device__ __half g_v[S_LEN * KV_DIM];
__device__ __half g_attn[S_LEN * DIM];

// ---------------------------------------------------------------------------
// helpers
// ---------------------------------------------------------------------------
__device__ __forceinline__ unsigned smem_u32(const void* p) {
    unsigned a;
    asm("{ .reg .u64 t; cvta.to.shared.u64 t, %1; cvt.u32.u64 %0, t; }" : "=r"(a) : "l"(p));
    return a;
}

__device__ __forceinline__ void mma_f16(float c[4], const unsigned a[4], const unsigned b[2]) {
    asm volatile(
        "mma.sync.aligned.m16n8k16.row.col.f32.f16.f16.f32 "
        "{%0,%1,%2,%3},{%4,%5,%6,%7},{%8,%9},{%0,%1,%2,%3};"
        : "+f"(c[0]), "+f"(c[1]), "+f"(c[2]), "+f"(c[3])
        : "r"(a[0]), "r"(a[1]), "r"(a[2]), "r"(a[3]), "r"(b[0]), "r"(b[1]));
}

__device__ __forceinline__ void ldsm4(unsigned r[4], unsigned addr) {
    asm volatile("ldmatrix.sync.aligned.m8n8.x4.shared.b16 {%0,%1,%2,%3}, [%4];"
                 : "=r"(r[0]), "=r"(r[1]), "=r"(r[2]), "=r"(r[3]) : "r"(addr));
}

__device__ __forceinline__ void ldsm4t(unsigned r[4], unsigned addr) {
    asm volatile("ldmatrix.sync.aligned.m8n8.x4.trans.shared.b16 {%0,%1,%2,%3}, [%4];"
                 : "=r"(r[0]), "=r"(r[1]), "=r"(r[2]), "=r"(r[3]) : "r"(addr));
}

__device__ __forceinline__ void cpa16(unsigned dst, const void* src) {
    asm volatile("cp.async.cg.shared.global [%0], [%1], 16;" :: "r"(dst), "l"(src));
}

// ---------------------------------------------------------------------------
// fp32 -> fp16 conversion (2 float4 per thread for ILP)
// ---------------------------------------------------------------------------
__global__ void cvt_f16(const float* __restrict__ s, __half* __restrict__ d, int n4) {
    int i = (blockIdx.x * 256 + threadIdx.x) * 2;
    if (i >= n4) return;
    float4 v0 = ((const float4*)s)[i];
    float4 v1 = ((const float4*)s)[i + 1];
    ((__half2*)d)[2 * i]     = __floats2half2_rn(v0.x, v0.y);
    ((__half2*)d)[2 * i + 1] = __floats2half2_rn(v0.z, v0.w);
    ((__half2*)d)[2 * i + 2] = __floats2half2_rn(v1.x, v1.y);
    ((__half2*)d)[2 * i + 3] = __floats2half2_rn(v1.z, v1.w);
}

// ---------------------------------------------------------------------------
// fp16 GEMM (unchanged from R5): CTA 128x256, K-step 32, 3-stage cp.async.
// ---------------------------------------------------------------------------
#define AST 40
#define A_H (128 * AST)
#define B_H (256 * AST)
#define STAGE_BYTES ((A_H + B_H) * 2)
#define GSMEM (3 * STAGE_BYTES)

__device__ __forceinline__ void g_load_stage(unsigned sbuf, const __half* Ap,
                                             const __half* Bp, int kt, int K, int tid) {
#pragma unroll
    for (int t = 0; t < 2; t++) {
        int idx = tid + t * 256;
        int row = idx >> 2, ch = idx & 3;
        cpa16(sbuf + (row * AST + ch * 8) * 2, Ap + (size_t)row * K + kt + ch * 8);
    }
#pragma unroll
    for (int t = 0; t < 4; t++) {
        int idx = tid + t * 256;
        int row = idx >> 2, ch = idx & 3;
        cpa16(sbuf + (A_H + row * AST + ch * 8) * 2, Bp + (size_t)row * K + kt + ch * 8);
    }
}

__global__ __launch_bounds__(256, 1)
void gemm_f16(const __half* __restrict__ Ah,
              const __half* __restrict__ B0, const __half* __restrict__ B1,
              const __half* __restrict__ B2,
              void* C0, void* C1, void* C2,
              int ldc0, int ldc1, int ldc2,
              int n1, int n2, int K, int out_f32) {
    extern __shared__ __align__(16) char smem[];
    const unsigned sbase = smem_u32(smem);
    const int tid = threadIdx.x, lane = tid & 31, warp = tid >> 5;
    const int mbase = (warp >> 2) * 64, nbase = (warp & 3) * 64;
    const int m0 = blockIdx.y * 128;
    const int nt = blockIdx.x;

    const __half* Bsel; void* Csel; int ldc, ncol0;
    if (nt < n1)      { Bsel = B0 + (size_t)nt * 256 * K;        Csel = C0; ldc = ldc0; ncol0 = nt * 256; }
    else if (nt < n2) { Bsel = B1 + (size_t)(nt - n1) * 256 * K; Csel = C1; ldc = ldc1; ncol0 = (nt - n1) * 256; }
    else              { Bsel = B2 + (size_t)(nt - n2) * 256 * K; Csel = C2; ldc = ldc2; ncol0 = (nt - n2) * 256; }
    const __half* Ap = Ah + (size_t)m0 * K;

    float acc[4][8][4];
#pragma unroll
    for (int i = 0; i < 4; i++)
#pragma unroll
        for (int j = 0; j < 8; j++)
#pragma unroll
            for (int r = 0; r < 4; r++) acc[i][j][r] = 0.f;

    const int NS = K / 32;
    g_load_stage(sbase, Ap, Bsel, 0, K, tid);
    asm volatile("cp.async.commit_group;" ::: "memory");
    g_load_stage(sbase + STAGE_BYTES, Ap, Bsel, 32, K, tid);
    asm volatile("cp.async.commit_group;" ::: "memory");

    for (int s = 0; s < NS; s++) {
        if (s <= NS - 2) asm volatile("cp.async.wait_group 1;" ::: "memory");
        else             asm volatile("cp.async.wait_group 0;" ::: "memory");
        __syncthreads();
        if (s + 2 < NS) {
            g_load_stage(sbase + ((s + 2) % 3) * STAGE_BYTES, Ap, Bsel, (s + 2) * 32, K, tid);
            asm volatile("cp.async.commit_group;" ::: "memory");
        }
        const unsigned sA = sbase + (s % 3) * STAGE_BYTES;
        const unsigned sB = sA + A_H * 2;
#pragma unroll
        for (int kc = 0; kc < 32; kc += 16) {
            unsigned a[4][4], b[8][2];
#pragma unroll
            for (int mt = 0; mt < 4; mt++)
                ldsm4(a[mt], sA + ((mbase + mt * 16 + (lane & 15)) * AST + kc + (lane >> 4) * 8) * 2);
#pragma unroll
            for (int p = 0; p < 4; p++) {
                unsigned t4[4];
                ldsm4(t4, sB + ((nbase + p * 16 + (lane & 15)) * AST + kc + (lane >> 4) * 8) * 2);
                b[2 * p][0] = t4[0]; b[2 * p][1] = t4[2];
                b[2 * p + 1][0] = t4[1]; b[2 * p + 1][1] = t4[3];
            }
#pragma unroll
            for (int mt = 0; mt < 4; mt++)
#pragma unroll
                for (int n8 = 0; n8 < 8; n8++)
                    mma_f16(acc[mt][n8], a[mt], b[n8]);
        }
        __syncthreads();
    }

#pragma unroll
    for (int mt = 0; mt < 4; mt++) {
        int row0 = m0 + mbase + mt * 16 + (lane >> 2);
#pragma unroll
        for (int n8 = 0; n8 < 8; n8++) {
            int col = ncol0 + nbase + n8 * 8 + 2 * (lane & 3);
            if (out_f32) {
                float* Cp = (float*)Csel;
                *(float2*)(Cp + (size_t)row0 * ldc + col)       = make_float2(acc[mt][n8][0], acc[mt][n8][1]);
                *(float2*)(Cp + (size_t)(row0 + 8) * ldc + col) = make_float2(acc[mt][n8][2], acc[mt][n8][3]);
            } else {
                __half* Cp = (__half*)Csel;
                *(__half2*)(Cp + (size_t)row0 * ldc + col)       = __floats2half2_rn(acc[mt][n8][0], acc[mt][n8][1]);
                *(__half2*)(Cp + (size_t)(row0 + 8) * ldc + col) = __floats2half2_rn(acc[mt][n8][2], acc[mt][n8][3]);
            }
        }
    }
}

// ---------------------------------------------------------------------------
// Merged RMSNorm + RoPE for q and k in one launch. grid=(S, NH+NKV).
// ---------------------------------------------------------------------------
__global__ void rmsnorm_rope_kernel(__half* __restrict__ qb, __half* __restrict__ kb,
                                    const float* __restrict__ qw_,
                                    const float* __restrict__ kw_,
                                    const float* __restrict__ cosp,
                                    const float* __restrict__ sinp) {
    const int s = blockIdx.x, hh = blockIdx.y, d = threadIdx.x;
    __half* p;
    const float* w;
    if (hh < NH) { p = qb + (size_t)s * DIM + hh * HD; w = qw_; }
    else         { p = kb + (size_t)s * KV_DIM + (hh - NH) * HD; w = kw_; }
    float v = __half2float(p[d]);
    float sq = v * v;
#pragma unroll
    for (int off = 16; off > 0; off >>= 1)
        sq += __shfl_xor_sync(0xffffffffu, sq, off);
    __shared__ float red[4];
    __shared__ float xs[HD];
    if ((d & 31) == 0) red[d >> 5] = sq;
    __syncthreads();
    float sum = red[0] + red[1] + red[2] + red[3];
    float r = rsqrtf(sum * (1.0f / HD) + 1e-6f);
    float xn = v * r * w[d];
    xs[d] = xn;
    __syncthreads();
    float rot = (d < 64) ? -xs[d + 64] : xs[d - 64];
    p[d] = __float2half_rn(xn * cosp[(size_t)s * HD + d] + rot * sinp[(size_t)s * HD + d]);
}

// ---------------------------------------------------------------------------
// Flash attention, fp16 mma. BM=128, BN=64, 256 threads (8 warps x 16 rows).
// K/V double-buffered via cp.async (load nt+1 overlaps compute nt).
// One __syncthreads per KV tile; P->PV needs only __syncwarp.
// ---------------------------------------------------------------------------
#define FQS 136
#define FPS 72
#define SQ_H   (128 * FQS)
#define SK_H   (64 * FQS)
#define FLASH_SMEM ((SQ_H + 4 * SK_H + 128 * FPS) * 2)   // 122880 B

__device__ __forceinline__ void fa_load_kv(unsigned dstK, unsigned dstV,
                                           const __half* Kp, const __half* Vp,
                                           int n0, int kvh, int tid) {
#pragma unroll
    for (int t = 0; t < 4; t++) {
        int idx = tid + t * 256;
        int row = idx >> 4, ch = idx & 15;
        size_t g = (size_t)(n0 + row) * KV_DIM + kvh * HD + ch * 8;
        cpa16(dstK + (row * FQS + ch * 8) * 2, Kp + g);
        cpa16(dstV + (row * FQS + ch * 8) * 2, Vp + g);
    }
}

__global__ __launch_bounds__(256, 1)
void flash_f16(const __half* __restrict__ Q, const __half* __restrict__ K,
               const __half* __restrict__ V, __half* __restrict__ O) {
    extern __shared__ __align__(16) char fsm[];
    __half* sQ = (__half*)fsm;
    const unsigned uQ = smem_u32(sQ);
    const unsigned uK0 = uQ + SQ_H * 2;
    const unsigned uK1 = uK0 + SK_H * 2;
    const unsigned uV0 = uK1 + SK_H * 2;
    const unsigned uV1 = uV0 + SK_H * 2;
    const unsigned uP = uV1 + SK_H * 2;

    const int tid = threadIdx.x, lane = tid & 31, warp = tid >> 5;
    const int mtb = (gridDim.x - 1) - blockIdx.x;    // longest-first
    const int h = blockIdx.y;
    const int kvh = h >> 2;
    const int m0 = mtb * 128;
    const int NT = (m0 + 128) / 64;

    // Q tile 128x128 via cp.async (group 0 together with K0/V0)
#pragma unroll
    for (int t = 0; t < 8; t++) {
        int idx = tid + t * 256;
        int row = idx >> 4, ch = idx & 15;
        cpa16(uQ + (row * FQS + ch * 8) * 2,
              Q + (size_t)(m0 + row) * DIM + h * HD + ch * 8);
    }
    fa_load_kv(uK0, uV0, K, V, 0, kvh, tid);
    asm volatile("cp.async.commit_group;" ::: "memory");

    float o[16][4];
    float mi[2] = {-1e30f, -1e30f}, li[2] = {0.f, 0.f};
#pragma unroll
    for (int i = 0; i < 16; i++)
#pragma unroll
        for (int j = 0; j < 4; j++) o[i][j] = 0.f;

    const float sc = 0.08838834764831845f;
    const int gr0 = m0 + warp * 16 + (lane >> 2), gr1 = gr0 + 8;

    for (int nt = 0; nt < NT; nt++) {
        const int n0 = nt * 64;
        const unsigned uK = (nt & 1) ? uK1 : uK0;
        const unsigned uV = (nt & 1) ? uV1 : uV0;

        asm volatile("cp.async.wait_group 0;" ::: "memory");
        __syncthreads();

        // prefetch next K/V into other buffer (overlaps compute below)
        if (nt + 1 < NT) {
            fa_load_kv((nt & 1) ? uK0 : uK1, (nt & 1) ? uV0 : uV1,
                       K, V, (nt + 1) * 64, kvh, tid);
            asm volatile("cp.async.commit_group;" ::: "memory");
        }

        // S = Q K^T  (warp rows warp*16..+15, cols 0..63)
        float s[8][4];
#pragma unroll
        for (int i = 0; i < 8; i++)
#pragma unroll
            for (int j = 0; j < 4; j++) s[i][j] = 0.f;

#pragma unroll
        for (int kc = 0; kc < 8; kc++) {
            unsigned a[4], b[8][2];
            ldsm4(a, uQ + ((warp * 16 + (lane & 15)) * FQS + kc * 16 + (lane >> 4) * 8) * 2);
#pragma unroll
            for (int p = 0; p < 4; p++) {
                unsigned t4[4];
                ldsm4(t4, uK + ((p * 16 + (lane & 15)) * FQS + kc * 16 + (lane >> 4) * 8) * 2);
                b[2 * p][0] = t4[0]; b[2 * p][1] = t4[2];
                b[2 * p + 1][0] = t4[1]; b[2 * p + 1][1] = t4[3];
            }
#pragma unroll
            for (int n8 = 0; n8 < 8; n8++)
                mma_f16(s[n8], a, b[n8]);
        }

        // scale + causal mask (only possibly-diagonal tiles)
        const bool diag = (n0 + 63 >= m0);
#pragma unroll
        for (int n8 = 0; n8 < 8; n8++) {
            int gc = n0 + n8 * 8 + 2 * (lane & 3);
            s[n8][0] *= sc; s[n8][1] *= sc; s[n8][2] *= sc; s[n8][3] *= sc;
            if (diag) {
                if (gc     > gr0) s[n8][0] = -1e30f;
                if (gc + 1 > gr0) s[n8][1] = -1e30f;
                if (gc     > gr1) s[n8][2] = -1e30f;
                if (gc + 1 > gr1) s[n8][3] = -1e30f;
            }
        }

        // online softmax
#pragma unroll
        for (int rr = 0; rr < 2; rr++) {
            float mloc = -1e30f;
#pragma unroll
            for (int n8 = 0; n8 < 8; n8++)
                mloc = fmaxf(mloc, fmaxf(s[n8][2 * rr], s[n8][2 * rr + 1]));
            mloc = fmaxf(mloc, __shfl_xor_sync(0xffffffffu, mloc, 1));
            mloc = fmaxf(mloc, __shfl_xor_sync(0xffffffffu, mloc, 2));
            float mnew = fmaxf(mi[rr], mloc);
            float corr = __expf(mi[rr] - mnew);
            float rs = 0.f;
#pragma unroll
            for (int n8 = 0; n8 < 8; n8++) {
                float p0 = __expf(s[n8][2 * rr] - mnew);
                float p1 = __expf(s[n8][2 * rr + 1] - mnew);
                s[n8][2 * rr] = p0; s[n8][2 * rr + 1] = p1;
                rs += p0 + p1;
            }
            rs += __shfl_xor_sync(0xffffffffu, rs, 1);
            rs += __shfl_xor_sync(0xffffffffu, rs, 2);
            li[rr] = li[rr] * corr + rs;
            mi[rr] = mnew;
#pragma unroll
            for (int i = 0; i < 16; i++) {
                o[i][2 * rr]     *= corr;
                o[i][2 * rr + 1] *= corr;
            }
            int prow = warp * 16 + (lane >> 2) + rr * 8;
#pragma unroll
            for (int n8 = 0; n8 < 8; n8++) {
                int pc = n8 * 8 + 2 * (lane & 3);
                *(__half2*)((__half*)fsm + (uP - uQ) / 2 + prow * FPS + pc) =
                    __floats2half2_rn(s[n8][2 * rr], s[n8][2 * rr + 1]);
            }
        }
        __syncwarp();   // P rows of this warp visible to this warp's ldmatrix

        // O += P @ V  (P rows own-warp; V^T frags via ldmatrix.trans)
#pragma unroll
        for (int kc = 0; kc < 4; kc++) {
            unsigned a[4];
            ldsm4(a, uP + ((warp * 16 + (lane & 15)) * FPS + kc * 16 + (lane >> 4) * 8) * 2);
#pragma unroll
            for (int p = 0; p < 8; p++) {
                unsigned t4[4];
                ldsm4t(t4, uV + ((kc * 16 + ((lane >> 3) & 1) * 8 + (lane & 7)) * FQS
                                 + p * 16 + (lane >> 4) * 8) * 2);
                unsigned b0[2] = {t4[0], t4[1]};
                unsigned b1[2] = {t4[2], t4[3]};
                mma_f16(o[2 * p], a, b0);
                mma_f16(o[2 * p + 1], a, b1);
            }
        }
        __syncthreads();   // all warps done with K/V[buf] before its reuse
    }

    // epilogue
    float inv0 = 1.f / li[0], inv1 = 1.f / li[1];
    const int row0 = m0 + warp * 16 + (lane >> 2);
#pragma unroll
    for (int n16 = 0; n16 < 16; n16++) {
        int gc = n16 * 8 + 2 * (lane & 3);
        *(__half2*)(O + (size_t)row0 * DIM + h * HD + gc) =
            __floats2half2_rn(o[n16][0] * inv0, o[n16][1] * inv0);
        *(__half2*)(O + (size_t)(row0 + 8) * DIM + h * HD + gc) =
            __floats2half2_rn(o[n16][2] * inv1, o[n16][3] * inv1);
    }
}

// ---------------------------------------------------------------------------
extern "C" void kernel_launch(void* const* d_in, const int* in_sizes, int n_in,
                              void* d_out, int out_size) {
    const float* x    = (const float*)d_in[0];
    const float* cosp = (const float*)d_in[1];
    const float* sinp = (const float*)d_in[2];
    const float* wq   = (const float*)d_in[3];
    const float* wk   = (const float*)d_in[4];
    const float* wv   = (const float*)d_in[5];
    const float* wo   = (const float*)d_in[6];
    const float* qw   = (const float*)d_in[7];
    const float* kw   = (const float*)d_in[8];
    float* out = (float*)d_out;

    __half *xh, *wqh, *wkh, *wvh, *woh, *q, *k, *v, *attn;
    cudaGetSymbolAddress((void**)&xh, g_xh);
    cudaGetSymbolAddress((void**)&wqh, g_wqh);
    cudaGetSymbolAddress((void**)&wkh, g_wkh);
    cudaGetSymbolAddress((void**)&wvh, g_wvh);
    cudaGetSymbolAddress((void**)&woh, g_woh);
    cudaGetSymbolAddress((void**)&q, g_q);
    cudaGetSymbolAddress((void**)&k, g_k);
    cudaGetSymbolAddress((void**)&v, g_v);
    cudaGetSymbolAddress((void**)&attn, g_attn);

    cudaFuncSetAttribute(gemm_f16, cudaFuncAttributeMaxDynamicSharedMemorySize, GSMEM);
    cudaFuncSetAttribute(flash_f16, cudaFuncAttributeMaxDynamicSharedMemorySize, FLASH_SMEM);

    // fp32 -> fp16 (2 float4 per thread)
    cvt_f16<<<(S_LEN * DIM / 8) / 256, 256>>>(x, xh, S_LEN * DIM / 4);
    cvt_f16<<<(DIM * DIM / 8) / 256, 256>>>(wq, wqh, DIM * DIM / 4);
    cvt_f16<<<(KV_DIM * DIM / 8) / 256, 256>>>(wk, wkh, KV_DIM * DIM / 4);
    cvt_f16<<<(KV_DIM * DIM / 8) / 256, 256>>>(wv, wvh, KV_DIM * DIM / 4);
    cvt_f16<<<(DIM * DIM / 8) / 256, 256>>>(wo, woh, DIM * DIM / 4);

    // fused QKV projection: 24 N-tiles of 256 (16 Q | 4 K | 4 V), f16 out
    gemm_f16<<<dim3(24, S_LEN / 128), 256, GSMEM>>>(
        xh, wqh, wkh, wvh, q, k, v, DIM, KV_DIM, KV_DIM, 16, 20, DIM, 0);

    // merged rmsnorm+rope for q and k
    rmsnorm_rope_kernel<<<dim3(S_LEN, NH + NKV), HD>>>(q, k, qw, kw, cosp, sinp);

    flash_f16<<<dim3(S_LEN / 128, NH), 256, FLASH_SMEM>>>(q, k, v, attn);

    // output projection: 16 N-tiles of 256, f32 out
    gemm_f16<<<dim3(16, S_LEN / 128), 256, GSMEM>>>(
        attn, woh, woh, woh, out, out, out, DIM, DIM, DIM, 16, 20, DIM, 1);
}

// round 8
// speedup vs baseline: 5.9677x; 1.0179x over previous
#include <cuda_runtime.h>
#include <cuda_fp16.h>
#include <math.h>

#define S_LEN 2048
#define DIM 4096
#define NH 32
#define NKV 8
#define HD 128
#define KV_DIM 1024

// f16 scratch (allocation-free rule: __device__ globals)
__device__ __half g_xh[S_LEN * DIM];
__device__ __half g_wqh[DIM * DIM];
__device__ __half g_wkh[KV_DIM * DIM];
__device__ __half g_wvh[KV_DIM * DIM];
__device__ __half g_woh[DIM * DIM];
__device__ __half g_q[S_LEN * DIM];
__device__ __half g_k[S_LEN * KV_DIM];
__device__ __half g_v[S_LEN * KV_DIM];
__device__ __half g_attn[S_LEN * DIM];

// ---------------------------------------------------------------------------
// helpers
// ---------------------------------------------------------------------------
__device__ __forceinline__ unsigned smem_u32(const void* p) {
    unsigned a;
    asm("{ .reg .u64 t; cvta.to.shared.u64 t, %1; cvt.u32.u64 %0, t; }" : "=r"(a) : "l"(p));
    return a;
}

__device__ __forceinline__ void mma_f16(float c[4], const unsigned a[4], const unsigned b[2]) {
    asm volatile(
        "mma.sync.aligned.m16n8k16.row.col.f32.f16.f16.f32 "
        "{%0,%1,%2,%3},{%4,%5,%6,%7},{%8,%9},{%0,%1,%2,%3};"
        : "+f"(c[0]), "+f"(c[1]), "+f"(c[2]), "+f"(c[3])
        : "r"(a[0]), "r"(a[1]), "r"(a[2]), "r"(a[3]), "r"(b[0]), "r"(b[1]));
}

__device__ __forceinline__ void ldsm4(unsigned r[4], unsigned addr) {
    asm volatile("ldmatrix.sync.aligned.m8n8.x4.shared.b16 {%0,%1,%2,%3}, [%4];"
                 : "=r"(r[0]), "=r"(r[1]), "=r"(r[2]), "=r"(r[3]) : "r"(addr));
}

__device__ __forceinline__ void ldsm4t(unsigned r[4], unsigned addr) {
    asm volatile("ldmatrix.sync.aligned.m8n8.x4.trans.shared.b16 {%0,%1,%2,%3}, [%4];"
                 : "=r"(r[0]), "=r"(r[1]), "=r"(r[2]), "=r"(r[3]) : "r"(addr));
}

__device__ __forceinline__ void cpa16(unsigned dst, const void* src) {
    asm volatile("cp.async.cg.shared.global [%0], [%1], 16;" :: "r"(dst), "l"(src));
}

// ---------------------------------------------------------------------------
// single merged fp32 -> fp16 conversion for x, wq, wk, wv, wo
// segment boundaries in elements (all multiples of 8)
// ---------------------------------------------------------------------------
#define SEG_X  8388608ull     // 2048*4096
#define SEG_WQ 25165824ull    // + 4096*4096
#define SEG_WK 29360128ull    // + 1024*4096
#define SEG_WV 33554432ull    // + 1024*4096
#define SEG_WO 50331648ull    // + 4096*4096

__global__ void cvt_all(const float* __restrict__ x,  const float* __restrict__ wq,
                        const float* __restrict__ wk, const float* __restrict__ wv,
                        const float* __restrict__ wo,
                        __half* xh, __half* wqh, __half* wkh, __half* wvh, __half* woh) {
    size_t i = ((size_t)blockIdx.x * 256 + threadIdx.x) * 8;
    if (i >= SEG_WO) return;
    const float* s; __half* d; size_t off;
    if (i < SEG_X)       { s = x;  d = xh;  off = i; }
    else if (i < SEG_WQ) { s = wq; d = wqh; off = i - SEG_X; }
    else if (i < SEG_WK) { s = wk; d = wkh; off = i - SEG_WQ; }
    else if (i < SEG_WV) { s = wv; d = wvh; off = i - SEG_WK; }
    else                 { s = wo; d = woh; off = i - SEG_WV; }
    float4 v0 = ((const float4*)(s + off))[0];
    float4 v1 = ((const float4*)(s + off))[1];
    __half2* dp = (__half2*)(d + off);
    dp[0] = __floats2half2_rn(v0.x, v0.y);
    dp[1] = __floats2half2_rn(v0.z, v0.w);
    dp[2] = __floats2half2_rn(v1.x, v1.y);
    dp[3] = __floats2half2_rn(v1.z, v1.w);
}

// ---------------------------------------------------------------------------
// fp16 GEMM (unchanged): CTA 128x256, K-step 32, 3-stage cp.async.
// ---------------------------------------------------------------------------
#define AST 40
#define A_H (128 * AST)
#define B_H (256 * AST)
#define STAGE_BYTES ((A_H + B_H) * 2)
#define GSMEM (3 * STAGE_BYTES)

__device__ __forceinline__ void g_load_stage(unsigned sbuf, const __half* Ap,
                                             const __half* Bp, int kt, int K, int tid) {
#pragma unroll
    for (int t = 0; t < 2; t++) {
        int idx = tid + t * 256;
        int row = idx >> 2, ch = idx & 3;
        cpa16(sbuf + (row * AST + ch * 8) * 2, Ap + (size_t)row * K + kt + ch * 8);
    }
#pragma unroll
    for (int t = 0; t < 4; t++) {
        int idx = tid + t * 256;
        int row = idx >> 2, ch = idx & 3;
        cpa16(sbuf + (A_H + row * AST + ch * 8) * 2, Bp + (size_t)row * K + kt + ch * 8);
    }
}

__global__ __launch_bounds__(256, 1)
void gemm_f16(const __half* __restrict__ Ah,
              const __half* __restrict__ B0, const __half* __restrict__ B1,
              const __half* __restrict__ B2,
              void* C0, void* C1, void* C2,
              int ldc0, int ldc1, int ldc2,
              int n1, int n2, int K, int out_f32) {
    extern __shared__ __align__(16) char smem[];
    const unsigned sbase = smem_u32(smem);
    const int tid = threadIdx.x, lane = tid & 31, warp = tid >> 5;
    const int mbase = (warp >> 2) * 64, nbase = (warp & 3) * 64;
    const int m0 = blockIdx.y * 128;
    const int nt = blockIdx.x;

    const __half* Bsel; void* Csel; int ldc, ncol0;
    if (nt < n1)      { Bsel = B0 + (size_t)nt * 256 * K;        Csel = C0; ldc = ldc0; ncol0 = nt * 256; }
    else if (nt < n2) { Bsel = B1 + (size_t)(nt - n1) * 256 * K; Csel = C1; ldc = ldc1; ncol0 = (nt - n1) * 256; }
    else              { Bsel = B2 + (size_t)(nt - n2) * 256 * K; Csel = C2; ldc = ldc2; ncol0 = (nt - n2) * 256; }
    const __half* Ap = Ah + (size_t)m0 * K;

    float acc[4][8][4];
#pragma unroll
    for (int i = 0; i < 4; i++)
#pragma unroll
        for (int j = 0; j < 8; j++)
#pragma unroll
            for (int r = 0; r < 4; r++) acc[i][j][r] = 0.f;

    const int NS = K / 32;
    g_load_stage(sbase, Ap, Bsel, 0, K, tid);
    asm volatile("cp.async.commit_group;" ::: "memory");
    g_load_stage(sbase + STAGE_BYTES, Ap, Bsel, 32, K, tid);
    asm volatile("cp.async.commit_group;" ::: "memory");

    for (int s = 0; s < NS; s++) {
        if (s <= NS - 2) asm volatile("cp.async.wait_group 1;" ::: "memory");
        else             asm volatile("cp.async.wait_group 0;" ::: "memory");
        __syncthreads();
        if (s + 2 < NS) {
            g_load_stage(sbase + ((s + 2) % 3) * STAGE_BYTES, Ap, Bsel, (s + 2) * 32, K, tid);
            asm volatile("cp.async.commit_group;" ::: "memory");
        }
        const unsigned sA = sbase + (s % 3) * STAGE_BYTES;
        const unsigned sB = sA + A_H * 2;
#pragma unroll
        for (int kc = 0; kc < 32; kc += 16) {
            unsigned a[4][4], b[8][2];
#pragma unroll
            for (int mt = 0; mt < 4; mt++)
                ldsm4(a[mt], sA + ((mbase + mt * 16 + (lane & 15)) * AST + kc + (lane >> 4) * 8) * 2);
#pragma unroll
            for (int p = 0; p < 4; p++) {
                unsigned t4[4];
                ldsm4(t4, sB + ((nbase + p * 16 + (lane & 15)) * AST + kc + (lane >> 4) * 8) * 2);
                b[2 * p][0] = t4[0]; b[2 * p][1] = t4[2];
                b[2 * p + 1][0] = t4[1]; b[2 * p + 1][1] = t4[3];
            }
#pragma unroll
            for (int mt = 0; mt < 4; mt++)
#pragma unroll
                for (int n8 = 0; n8 < 8; n8++)
                    mma_f16(acc[mt][n8], a[mt], b[n8]);
        }
        __syncthreads();
    }

#pragma unroll
    for (int mt = 0; mt < 4; mt++) {
        int row0 = m0 + mbase + mt * 16 + (lane >> 2);
#pragma unroll
        for (int n8 = 0; n8 < 8; n8++) {
            int col = ncol0 + nbase + n8 * 8 + 2 * (lane & 3);
            if (out_f32) {
                float* Cp = (float*)Csel;
                *(float2*)(Cp + (size_t)row0 * ldc + col)       = make_float2(acc[mt][n8][0], acc[mt][n8][1]);
                *(float2*)(Cp + (size_t)(row0 + 8) * ldc + col) = make_float2(acc[mt][n8][2], acc[mt][n8][3]);
            } else {
                __half* Cp = (__half*)Csel;
                *(__half2*)(Cp + (size_t)row0 * ldc + col)       = __floats2half2_rn(acc[mt][n8][0], acc[mt][n8][1]);
                *(__half2*)(Cp + (size_t)(row0 + 8) * ldc + col) = __floats2half2_rn(acc[mt][n8][2], acc[mt][n8][3]);
            }
        }
    }
}

// ---------------------------------------------------------------------------
// Merged RMSNorm + RoPE for q and k. grid=(S, NH+NKV).
// ---------------------------------------------------------------------------
__global__ void rmsnorm_rope_kernel(__half* __restrict__ qb, __half* __restrict__ kb,
                                    const float* __restrict__ qw_,
                                    const float* __restrict__ kw_,
                                    const float* __restrict__ cosp,
                                    const float* __restrict__ sinp) {
    const int s = blockIdx.x, hh = blockIdx.y, d = threadIdx.x;
    __half* p;
    const float* w;
    if (hh < NH) { p = qb + (size_t)s * DIM + hh * HD; w = qw_; }
    else         { p = kb + (size_t)s * KV_DIM + (hh - NH) * HD; w = kw_; }
    float v = __half2float(p[d]);
    float sq = v * v;
#pragma unroll
    for (int off = 16; off > 0; off >>= 1)
        sq += __shfl_xor_sync(0xffffffffu, sq, off);
    __shared__ float red[4];
    __shared__ float xs[HD];
    if ((d & 31) == 0) red[d >> 5] = sq;
    __syncthreads();
    float sum = red[0] + red[1] + red[2] + red[3];
    float r = rsqrtf(sum * (1.0f / HD) + 1e-6f);
    float xn = v * r * w[d];
    xs[d] = xn;
    __syncthreads();
    float rot = (d < 64) ? -xs[d + 64] : xs[d - 64];
    p[d] = __float2half_rn(xn * cosp[(size_t)s * HD + d] + rot * sinp[(size_t)s * HD + d]);
}

// ---------------------------------------------------------------------------
// Flash attention, fp16 mma. BM=128, BN=128, 256 threads (8 warps x 16 rows).
// One softmax pass / rescale / barrier per 128 kv cols. K/V double-buffered
// cp.async; 1 __syncthreads per tile; P->PV own-warp rows (syncwarp only).
// smem (halfs, stride 136): Q | K0 K1 V0 V1 | P  = 6*128*136*2 = 208896 B.
// ---------------------------------------------------------------------------
#define FQS 136
#define TILE_H (128 * FQS)
#define FLASH_SMEM (6 * TILE_H * 2)

__device__ __forceinline__ void fa_load_kv(unsigned dstK, unsigned dstV,
                                           const __half* Kp, const __half* Vp,
                                           int n0, int kvh, int tid) {
#pragma unroll
    for (int t = 0; t < 8; t++) {
        int idx = tid + t * 256;
        int row = idx >> 4, ch = idx & 15;
        size_t g = (size_t)(n0 + row) * KV_DIM + kvh * HD + ch * 8;
        cpa16(dstK + (row * FQS + ch * 8) * 2, Kp + g);
        cpa16(dstV + (row * FQS + ch * 8) * 2, Vp + g);
    }
}

__global__ __launch_bounds__(256, 1)
void flash_f16(const __half* __restrict__ Q, const __half* __restrict__ K,
               const __half* __restrict__ V, __half* __restrict__ O) {
    extern __shared__ __align__(16) char fsm[];
    __half* sP_ptr;
    const unsigned uQ = smem_u32(fsm);
    const unsigned uK0 = uQ + TILE_H * 2;
    const unsigned uK1 = uK0 + TILE_H * 2;
    const unsigned uV0 = uK1 + TILE_H * 2;
    const unsigned uV1 = uV0 + TILE_H * 2;
    const unsigned uP  = uV1 + TILE_H * 2;
    sP_ptr = (__half*)fsm + 5 * TILE_H;

    const int tid = threadIdx.x, lane = tid & 31, warp = tid >> 5;
    const int mtb = (gridDim.x - 1) - blockIdx.x;    // longest-first
    const int h = blockIdx.y;
    const int kvh = h >> 2;
    const int m0 = mtb * 128;
    const int NT = mtb + 1;

    // Q tile 128x128 + first K/V via cp.async, one group
#pragma unroll
    for (int t = 0; t < 8; t++) {
        int idx = tid + t * 256;
        int row = idx >> 4, ch = idx & 15;
        cpa16(uQ + (row * FQS + ch * 8) * 2,
              Q + (size_t)(m0 + row) * DIM + h * HD + ch * 8);
    }
    fa_load_kv(uK0, uV0, K, V, 0, kvh, tid);
    asm volatile("cp.async.commit_group;" ::: "memory");

    float o[16][4];
    float mi[2] = {-1e30f, -1e30f}, li[2] = {0.f, 0.f};
#pragma unroll
    for (int i = 0; i < 16; i++)
#pragma unroll
        for (int j = 0; j < 4; j++) o[i][j] = 0.f;

    const float sc = 0.08838834764831845f;
    const int lr = warp * 16 + (lane >> 2);          // local q row (and +8)
    const int gr0 = m0 + lr, gr1 = gr0 + 8;

    for (int nt = 0; nt < NT; nt++) {
        const int n0 = nt * 128;
        const unsigned uK = (nt & 1) ? uK1 : uK0;
        const unsigned uV = (nt & 1) ? uV1 : uV0;

        asm volatile("cp.async.wait_group 0;" ::: "memory");
        __syncthreads();           // data ready + all warps done with other buf

        if (nt + 1 < NT) {
            fa_load_kv((nt & 1) ? uK0 : uK1, (nt & 1) ? uV0 : uV1,
                       K, V, (nt + 1) * 128, kvh, tid);
            asm volatile("cp.async.commit_group;" ::: "memory");
        }

        // S = Q K^T : 16 n8-groups x 8 k-chunks
        float s[16][4];
#pragma unroll
        for (int i = 0; i < 16; i++)
#pragma unroll
            for (int j = 0; j < 4; j++) s[i][j] = 0.f;

#pragma unroll
        for (int kc = 0; kc < 8; kc++) {
            unsigned a[4];
            ldsm4(a, uQ + ((warp * 16 + (lane & 15)) * FQS + kc * 16 + (lane >> 4) * 8) * 2);
#pragma unroll
            for (int p = 0; p < 8; p++) {
                unsigned t4[4];
                ldsm4(t4, uK + ((p * 16 + (lane & 15)) * FQS + kc * 16 + (lane >> 4) * 8) * 2);
                unsigned b0[2] = {t4[0], t4[2]};
                unsigned b1[2] = {t4[1], t4[3]};
                mma_f16(s[2 * p], a, b0);
                mma_f16(s[2 * p + 1], a, b1);
            }
        }

        // scale + causal mask (only the diagonal tile nt == NT-1)
        const bool diag = (nt == NT - 1);
#pragma unroll
        for (int n8 = 0; n8 < 16; n8++) {
            int gc = n0 + n8 * 8 + 2 * (lane & 3);
            s[n8][0] *= sc; s[n8][1] *= sc; s[n8][2] *= sc; s[n8][3] *= sc;
            if (diag) {
                if (gc     > gr0) s[n8][0] = -1e30f;
                if (gc + 1 > gr0) s[n8][1] = -1e30f;
                if (gc     > gr1) s[n8][2] = -1e30f;
                if (gc + 1 > gr1) s[n8][3] = -1e30f;
            }
        }

        // online softmax (once per 128 cols)
#pragma unroll
        for (int rr = 0; rr < 2; rr++) {
            float mloc = -1e30f;
#pragma unroll
            for (int n8 = 0; n8 < 16; n8++)
                mloc = fmaxf(mloc, fmaxf(s[n8][2 * rr], s[n8][2 * rr + 1]));
            mloc = fmaxf(mloc, __shfl_xor_sync(0xffffffffu, mloc, 1));
            mloc = fmaxf(mloc, __shfl_xor_sync(0xffffffffu, mloc, 2));
            float mnew = fmaxf(mi[rr], mloc);
            float corr = __expf(mi[rr] - mnew);
            float rs = 0.f;
#pragma unroll
            for (int n8 = 0; n8 < 16; n8++) {
                float p0 = __expf(s[n8][2 * rr] - mnew);
                float p1 = __expf(s[n8][2 * rr + 1] - mnew);
                s[n8][2 * rr] = p0; s[n8][2 * rr + 1] = p1;
                rs += p0 + p1;
            }
            rs += __shfl_xor_sync(0xffffffffu, rs, 1);
            rs += __shfl_xor_sync(0xffffffffu, rs, 2);
            li[rr] = li[rr] * corr + rs;
            mi[rr] = mnew;
#pragma unroll
            for (int i = 0; i < 16; i++) {
                o[i][2 * rr]     *= corr;
                o[i][2 * rr + 1] *= corr;
            }
            int prow = warp * 16 + (lane >> 2) + rr * 8;
#pragma unroll
            for (int n8 = 0; n8 < 16; n8++) {
                int pc = n8 * 8 + 2 * (lane & 3);
                *(__half2*)(sP_ptr + prow * FQS + pc) =
                    __floats2half2_rn(s[n8][2 * rr], s[n8][2 * rr + 1]);
            }
        }
        __syncwarp();

        // O += P @ V  (P rows own-warp; V^T frags via ldmatrix.trans)
#pragma unroll
        for (int kc = 0; kc < 8; kc++) {
            unsigned a[4];
            ldsm4(a, uP + ((warp * 16 + (lane & 15)) * FQS + kc * 16 + (lane >> 4) * 8) * 2);
#pragma unroll
            for (int p = 0; p < 8; p++) {
                unsigned t4[4];
                ldsm4t(t4, uV + ((kc * 16 + ((lane >> 3) & 1) * 8 + (lane & 7)) * FQS
                                 + p * 16 + (lane >> 4) * 8) * 2);
                unsigned b0[2] = {t4[0], t4[1]};
                unsigned b1[2] = {t4[2], t4[3]};
                mma_f16(o[2 * p], a, b0);
                mma_f16(o[2 * p + 1], a, b1);
            }
        }
        // no trailing barrier: next iteration's top __syncthreads protects bufs
    }

    // epilogue
    float inv0 = 1.f / li[0], inv1 = 1.f / li[1];
    const int row0 = m0 + warp * 16 + (lane >> 2);
#pragma unroll
    for (int n16 = 0; n16 < 16; n16++) {
        int gc = n16 * 8 + 2 * (lane & 3);
        *(__half2*)(O + (size_t)row0 * DIM + h * HD + gc) =
            __floats2half2_rn(o[n16][0] * inv0, o[n16][1] * inv0);
        *(__half2*)(O + (size_t)(row0 + 8) * DIM + h * HD + gc) =
            __floats2half2_rn(o[n16][2] * inv1, o[n16][3] * inv1);
    }
}

// ---------------------------------------------------------------------------
extern "C" void kernel_launch(void* const* d_in, const int* in_sizes, int n_in,
                              void* d_out, int out_size) {
    const float* x    = (const float*)d_in[0];
    const float* cosp = (const float*)d_in[1];
    const float* sinp = (const float*)d_in[2];
    const float* wq   = (const float*)d_in[3];
    const float* wk   = (const float*)d_in[4];
    const float* wv   = (const float*)d_in[5];
    const float* wo   = (const float*)d_in[6];
    const float* qw   = (const float*)d_in[7];
    const float* kw   = (const float*)d_in[8];
    float* out = (float*)d_out;

    __half *xh, *wqh, *wkh, *wvh, *woh, *q, *k, *v, *attn;
    cudaGetSymbolAddress((void**)&xh, g_xh);
    cudaGetSymbolAddress((void**)&wqh, g_wqh);
    cudaGetSymbolAddress((void**)&wkh, g_wkh);
    cudaGetSymbolAddress((void**)&wvh, g_wvh);
    cudaGetSymbolAddress((void**)&woh, g_woh);
    cudaGetSymbolAddress((void**)&q, g_q);
    cudaGetSymbolAddress((void**)&k, g_k);
    cudaGetSymbolAddress((void**)&v, g_v);
    cudaGetSymbolAddress((void**)&attn, g_attn);

    cudaFuncSetAttribute(gemm_f16, cudaFuncAttributeMaxDynamicSharedMemorySize, GSMEM);
    cudaFuncSetAttribute(flash_f16, cudaFuncAttributeMaxDynamicSharedMemorySize, FLASH_SMEM);

    // one merged fp32 -> fp16 conversion (x + 4 weight matrices)
    cvt_all<<<(unsigned)((SEG_WO / 8 + 255) / 256), 256>>>(
        x, wq, wk, wv, wo, xh, wqh, wkh, wvh, woh);

    // fused QKV projection: 24 N-tiles of 256 (16 Q | 4 K | 4 V), f16 out
    gemm_f16<<<dim3(24, S_LEN / 128), 256, GSMEM>>>(
        xh, wqh, wkh, wvh, q, k, v, DIM, KV_DIM, KV_DIM, 16, 20, DIM, 0);

    // merged rmsnorm+rope for q and k
    rmsnorm_rope_kernel<<<dim3(S_LEN, NH + NKV), HD>>>(q, k, qw, kw, cosp, sinp);

    flash_f16<<<dim3(S_LEN / 128, NH), 256, FLASH_SMEM>>>(q, k, v, attn);

    // output projection: 16 N-tiles of 256, f32 out
    gemm_f16<<<dim3(16, S_LEN / 128), 256, GSMEM>>>(
        attn, woh, woh, woh, out, out, out, DIM, DIM, DIM, 16, 20, DIM, 1);
}

// round 9
// speedup vs baseline: 6.7360x; 1.1288x over previous
#include <cuda_runtime.h>
#include <cuda_fp16.h>
#include <math.h>

#define S_LEN 2048
#define DIM 4096
#define NH 32
#define NKV 8
#define HD 128
#define KV_DIM 1024

// f16 scratch (allocation-free rule: __device__ globals)
__device__ __half g_xh[S_LEN * DIM];
__device__ __half g_wqh[DIM * DIM];
__device__ __half g_wkh[KV_DIM * DIM];
__device__ __half g_wvh[KV_DIM * DIM];
__device__ __half g_woh[DIM * DIM];
__device__ __half g_q[S_LEN * DIM];
__device__ __half g_k[S_LEN * KV_DIM];
__device__ __half g_v[S_LEN * KV_DIM];
__device__ __half g_attn[S_LEN * DIM];

// ---------------------------------------------------------------------------
// helpers
// ---------------------------------------------------------------------------
__device__ __forceinline__ unsigned smem_u32(const void* p) {
    unsigned a;
    asm("{ .reg .u64 t; cvta.to.shared.u64 t, %1; cvt.u32.u64 %0, t; }" : "=r"(a) : "l"(p));
    return a;
}

__device__ __forceinline__ void mma_f16(float c[4], const unsigned a[4], const unsigned b[2]) {
    asm volatile(
        "mma.sync.aligned.m16n8k16.row.col.f32.f16.f16.f32 "
        "{%0,%1,%2,%3},{%4,%5,%6,%7},{%8,%9},{%0,%1,%2,%3};"
        : "+f"(c[0]), "+f"(c[1]), "+f"(c[2]), "+f"(c[3])
        : "r"(a[0]), "r"(a[1]), "r"(a[2]), "r"(a[3]), "r"(b[0]), "r"(b[1]));
}

__device__ __forceinline__ void ldsm4(unsigned r[4], unsigned addr) {
    asm volatile("ldmatrix.sync.aligned.m8n8.x4.shared.b16 {%0,%1,%2,%3}, [%4];"
                 : "=r"(r[0]), "=r"(r[1]), "=r"(r[2]), "=r"(r[3]) : "r"(addr));
}

__device__ __forceinline__ void ldsm4t(unsigned r[4], unsigned addr) {
    asm volatile("ldmatrix.sync.aligned.m8n8.x4.trans.shared.b16 {%0,%1,%2,%3}, [%4];"
                 : "=r"(r[0]), "=r"(r[1]), "=r"(r[2]), "=r"(r[3]) : "r"(addr));
}

__device__ __forceinline__ void cpa16(unsigned dst, const void* src) {
    asm volatile("cp.async.cg.shared.global [%0], [%1], 16;" :: "r"(dst), "l"(src));
}

// pack two f32 into f16x2 (lo = a, hi = b), RN — same rounding as __floats2half2_rn
__device__ __forceinline__ unsigned packh2(float a, float b) {
    unsigned r;
    asm("cvt.rn.f16x2.f32 %0, %1, %2;" : "=r"(r) : "f"(b), "f"(a));
    return r;
}

// ---------------------------------------------------------------------------
// single merged fp32 -> fp16 conversion for x, wq, wk, wv, wo
// ---------------------------------------------------------------------------
#define SEG_X  8388608ull
#define SEG_WQ 25165824ull
#define SEG_WK 29360128ull
#define SEG_WV 33554432ull
#define SEG_WO 50331648ull

__global__ void cvt_all(const float* __restrict__ x,  const float* __restrict__ wq,
                        const float* __restrict__ wk, const float* __restrict__ wv,
                        const float* __restrict__ wo,
                        __half* xh, __half* wqh, __half* wkh, __half* wvh, __half* woh) {
    size_t i = ((size_t)blockIdx.x * 256 + threadIdx.x) * 8;
    if (i >= SEG_WO) return;
    const float* s; __half* d; size_t off;
    if (i < SEG_X)       { s = x;  d = xh;  off = i; }
    else if (i < SEG_WQ) { s = wq; d = wqh; off = i - SEG_X; }
    else if (i < SEG_WK) { s = wk; d = wkh; off = i - SEG_WQ; }
    else if (i < SEG_WV) { s = wv; d = wvh; off = i - SEG_WK; }
    else                 { s = wo; d = woh; off = i - SEG_WV; }
    float4 v0 = ((const float4*)(s + off))[0];
    float4 v1 = ((const float4*)(s + off))[1];
    __half2* dp = (__half2*)(d + off);
    dp[0] = __floats2half2_rn(v0.x, v0.y);
    dp[1] = __floats2half2_rn(v0.z, v0.w);
    dp[2] = __floats2half2_rn(v1.x, v1.y);
    dp[3] = __floats2half2_rn(v1.z, v1.w);
}

// ---------------------------------------------------------------------------
// fp16 GEMM: CTA 128x256, K-step 64, 3-stage cp.async, ONE sync per stage.
// ---------------------------------------------------------------------------
#define AST 72                              // 64 + 8 pad (halfs)
#define A_H (128 * AST)
#define B_H (256 * AST)
#define STAGE_BYTES ((A_H + B_H) * 2)       // 55296
#define GSMEM (3 * STAGE_BYTES)             // 165888

__device__ __forceinline__ void g_load_stage(unsigned sbuf, const __half* Ap,
                                             const __half* Bp, int kt, int K, int tid) {
#pragma unroll
    for (int t = 0; t < 4; t++) {           // A: 128 rows x 8 chunks
        int idx = tid + t * 256;
        int row = idx >> 3, ch = idx & 7;
        cpa16(sbuf + (row * AST + ch * 8) * 2, Ap + (size_t)row * K + kt + ch * 8);
    }
#pragma unroll
    for (int t = 0; t < 8; t++) {           // B: 256 rows x 8 chunks
        int idx = tid + t * 256;
        int row = idx >> 3, ch = idx & 7;
        cpa16(sbuf + (A_H + row * AST + ch * 8) * 2, Bp + (size_t)row * K + kt + ch * 8);
    }
}

__global__ __launch_bounds__(256, 1)
void gemm_f16(const __half* __restrict__ Ah,
              const __half* __restrict__ B0, const __half* __restrict__ B1,
              const __half* __restrict__ B2,
              void* C0, void* C1, void* C2,
              int ldc0, int ldc1, int ldc2,
              int n1, int n2, int K, int out_f32) {
    extern __shared__ __align__(16) char smem[];
    const unsigned sbase = smem_u32(smem);
    const int tid = threadIdx.x, lane = tid & 31, warp = tid >> 5;
    const int mbase = (warp >> 2) * 64, nbase = (warp & 3) * 64;
    const int m0 = blockIdx.y * 128;
    const int nt = blockIdx.x;

    const __half* Bsel; void* Csel; int ldc, ncol0;
    if (nt < n1)      { Bsel = B0 + (size_t)nt * 256 * K;        Csel = C0; ldc = ldc0; ncol0 = nt * 256; }
    else if (nt < n2) { Bsel = B1 + (size_t)(nt - n1) * 256 * K; Csel = C1; ldc = ldc1; ncol0 = (nt - n1) * 256; }
    else              { Bsel = B2 + (size_t)(nt - n2) * 256 * K; Csel = C2; ldc = ldc2; ncol0 = (nt - n2) * 256; }
    const __half* Ap = Ah + (size_t)m0 * K;

    float acc[4][8][4];
#pragma unroll
    for (int i = 0; i < 4; i++)
#pragma unroll
        for (int j = 0; j < 8; j++)
#pragma unroll
            for (int r = 0; r < 4; r++) acc[i][j][r] = 0.f;

    const int NS = K / 64;
    g_load_stage(sbase, Ap, Bsel, 0, K, tid);
    asm volatile("cp.async.commit_group;" ::: "memory");
    g_load_stage(sbase + STAGE_BYTES, Ap, Bsel, 64, K, tid);
    asm volatile("cp.async.commit_group;" ::: "memory");

    for (int s = 0; s < NS; s++) {
        if (s <= NS - 2) asm volatile("cp.async.wait_group 1;" ::: "memory");
        else             asm volatile("cp.async.wait_group 0;" ::: "memory");
        __syncthreads();
        if (s + 2 < NS) {
            g_load_stage(sbase + ((s + 2) % 3) * STAGE_BYTES, Ap, Bsel, (s + 2) * 64, K, tid);
            asm volatile("cp.async.commit_group;" ::: "memory");
        }
        const unsigned sA = sbase + (s % 3) * STAGE_BYTES;
        const unsigned sB = sA + A_H * 2;
#pragma unroll
        for (int kc = 0; kc < 64; kc += 16) {
            unsigned a[4][4], b[8][2];
#pragma unroll
            for (int mt = 0; mt < 4; mt++)
                ldsm4(a[mt], sA + ((mbase + mt * 16 + (lane & 15)) * AST + kc + (lane >> 4) * 8) * 2);
#pragma unroll
            for (int p = 0; p < 4; p++) {
                unsigned t4[4];
                ldsm4(t4, sB + ((nbase + p * 16 + (lane & 15)) * AST + kc + (lane >> 4) * 8) * 2);
                b[2 * p][0] = t4[0]; b[2 * p][1] = t4[2];
                b[2 * p + 1][0] = t4[1]; b[2 * p + 1][1] = t4[3];
            }
#pragma unroll
            for (int mt = 0; mt < 4; mt++)
#pragma unroll
                for (int n8 = 0; n8 < 8; n8++)
                    mma_f16(acc[mt][n8], a[mt], b[n8]);
        }
        // no bottom sync: next iteration's top __syncthreads orders buffer reuse
    }

#pragma unroll
    for (int mt = 0; mt < 4; mt++) {
        int row0 = m0 + mbase + mt * 16 + (lane >> 2);
#pragma unroll
        for (int n8 = 0; n8 < 8; n8++) {
            int col = ncol0 + nbase + n8 * 8 + 2 * (lane & 3);
            if (out_f32) {
                float* Cp = (float*)Csel;
                *(float2*)(Cp + (size_t)row0 * ldc + col)       = make_float2(acc[mt][n8][0], acc[mt][n8][1]);
                *(float2*)(Cp + (size_t)(row0 + 8) * ldc + col) = make_float2(acc[mt][n8][2], acc[mt][n8][3]);
            } else {
                __half* Cp = (__half*)Csel;
                *(__half2*)(Cp + (size_t)row0 * ldc + col)       = __floats2half2_rn(acc[mt][n8][0], acc[mt][n8][1]);
                *(__half2*)(Cp + (size_t)(row0 + 8) * ldc + col) = __floats2half2_rn(acc[mt][n8][2], acc[mt][n8][3]);
            }
        }
    }
}

// ---------------------------------------------------------------------------
// Merged RMSNorm + RoPE for q and k. grid=(S, NH+NKV).
// ---------------------------------------------------------------------------
__global__ void rmsnorm_rope_kernel(__half* __restrict__ qb, __half* __restrict__ kb,
                                    const float* __restrict__ qw_,
                                    const float* __restrict__ kw_,
                                    const float* __restrict__ cosp,
                                    const float* __restrict__ sinp) {
    const int s = blockIdx.x, hh = blockIdx.y, d = threadIdx.x;
    __half* p;
    const float* w;
    if (hh < NH) { p = qb + (size_t)s * DIM + hh * HD; w = qw_; }
    else         { p = kb + (size_t)s * KV_DIM + (hh - NH) * HD; w = kw_; }
    float v = __half2float(p[d]);
    float sq = v * v;
#pragma unroll
    for (int off = 16; off > 0; off >>= 1)
        sq += __shfl_xor_sync(0xffffffffu, sq, off);
    __shared__ float red[4];
    __shared__ float xs[HD];
    if ((d & 31) == 0) red[d >> 5] = sq;
    __syncthreads();
    float sum = red[0] + red[1] + red[2] + red[3];
    float r = rsqrtf(sum * (1.0f / HD) + 1e-6f);
    float xn = v * r * w[d];
    xs[d] = xn;
    __syncthreads();
    float rot = (d < 64) ? -xs[d + 64] : xs[d - 64];
    p[d] = __float2half_rn(xn * cosp[(size_t)s * HD + d] + rot * sinp[(size_t)s * HD + d]);
}

// ---------------------------------------------------------------------------
// Flash attention, fp16 mma. BM=BN=128, 256 threads (8 warps x 16 rows).
// Q fragments hoisted to registers; P stays in registers (S C-frag == PV
// A-frag layout). smem: Q | K0 K1 V0 V1 = 5*128*136*2 = 174080 B.
// ---------------------------------------------------------------------------
#define FQS 136
#define TILE_H (128 * FQS)
#define FLASH_SMEM (5 * TILE_H * 2)

__device__ __forceinline__ void fa_load_kv(unsigned dstK, unsigned dstV,
                                           const __half* Kp, const __half* Vp,
                                           int n0, int kvh, int tid) {
#pragma unroll
    for (int t = 0; t < 8; t++) {
        int idx = tid + t * 256;
        int row = idx >> 4, ch = idx & 15;
        size_t g = (size_t)(n0 + row) * KV_DIM + kvh * HD + ch * 8;
        cpa16(dstK + (row * FQS + ch * 8) * 2, Kp + g);
        cpa16(dstV + (row * FQS + ch * 8) * 2, Vp + g);
    }
}

__global__ __launch_bounds__(256, 1)
void flash_f16(const __half* __restrict__ Q, const __half* __restrict__ K,
               const __half* __restrict__ V, __half* __restrict__ O) {
    extern __shared__ __align__(16) char fsm[];
    const unsigned uQ = smem_u32(fsm);
    const unsigned uK0 = uQ + TILE_H * 2;
    const unsigned uK1 = uK0 + TILE_H * 2;
    const unsigned uV0 = uK1 + TILE_H * 2;
    const unsigned uV1 = uV0 + TILE_H * 2;

    const int tid = threadIdx.x, lane = tid & 31, warp = tid >> 5;
    const int mtb = (gridDim.x - 1) - blockIdx.x;    // longest-first
    const int h = blockIdx.y;
    const int kvh = h >> 2;
    const int m0 = mtb * 128;
    const int NT = mtb + 1;

    // Q tile + first K/V via cp.async, one group
#pragma unroll
    for (int t = 0; t < 8; t++) {
        int idx = tid + t * 256;
        int row = idx >> 4, ch = idx & 15;
        cpa16(uQ + (row * FQS + ch * 8) * 2,
              Q + (size_t)(m0 + row) * DIM + h * HD + ch * 8);
    }
    fa_load_kv(uK0, uV0, K, V, 0, kvh, tid);
    asm volatile("cp.async.commit_group;" ::: "memory");

    float o[16][4];
    float mi[2] = {-1e30f, -1e30f}, li[2] = {0.f, 0.f};
#pragma unroll
    for (int i = 0; i < 16; i++)
#pragma unroll
        for (int j = 0; j < 4; j++) o[i][j] = 0.f;

    unsigned qf[8][4];                               // hoisted Q fragments

    const float sc = 0.08838834764831845f;
    const int lr = warp * 16 + (lane >> 2);
    const int gr0 = m0 + lr, gr1 = gr0 + 8;

    for (int nt = 0; nt < NT; nt++) {
        const int n0 = nt * 128;
        const unsigned uK = (nt & 1) ? uK1 : uK0;
        const unsigned uV = (nt & 1) ? uV1 : uV0;

        asm volatile("cp.async.wait_group 0;" ::: "memory");
        __syncthreads();           // data ready + all warps done with other buf

        if (nt == 0) {             // Q fragments once, tile-invariant
#pragma unroll
            for (int kc = 0; kc < 8; kc++)
                ldsm4(qf[kc], uQ + ((warp * 16 + (lane & 15)) * FQS + kc * 16 + (lane >> 4) * 8) * 2);
        }
        if (nt + 1 < NT) {
            fa_load_kv((nt & 1) ? uK0 : uK1, (nt & 1) ? uV0 : uV1,
                       K, V, (nt + 1) * 128, kvh, tid);
            asm volatile("cp.async.commit_group;" ::: "memory");
        }

        // S = Q K^T : 16 n8-groups x 8 k-chunks
        float s[16][4];
#pragma unroll
        for (int i = 0; i < 16; i++)
#pragma unroll
            for (int j = 0; j < 4; j++) s[i][j] = 0.f;

#pragma unroll
        for (int kc = 0; kc < 8; kc++) {
#pragma unroll
            for (int p = 0; p < 8; p++) {
                unsigned t4[4];
                ldsm4(t4, uK + ((p * 16 + (lane & 15)) * FQS + kc * 16 + (lane >> 4) * 8) * 2);
                unsigned b0[2] = {t4[0], t4[2]};
                unsigned b1[2] = {t4[1], t4[3]};
                mma_f16(s[2 * p], qf[kc], b0);
                mma_f16(s[2 * p + 1], qf[kc], b1);
            }
        }

        // scale + causal mask (diagonal tile only)
        const bool diag = (nt == NT - 1);
#pragma unroll
        for (int n8 = 0; n8 < 16; n8++) {
            int gc = n0 + n8 * 8 + 2 * (lane & 3);
            s[n8][0] *= sc; s[n8][1] *= sc; s[n8][2] *= sc; s[n8][3] *= sc;
            if (diag) {
                if (gc     > gr0) s[n8][0] = -1e30f;
                if (gc + 1 > gr0) s[n8][1] = -1e30f;
                if (gc     > gr1) s[n8][2] = -1e30f;
                if (gc + 1 > gr1) s[n8][3] = -1e30f;
            }
        }

        // online softmax (once per 128 cols)
#pragma unroll
        for (int rr = 0; rr < 2; rr++) {
            float mloc = -1e30f;
#pragma unroll
            for (int n8 = 0; n8 < 16; n8++)
                mloc = fmaxf(mloc, fmaxf(s[n8][2 * rr], s[n8][2 * rr + 1]));
            mloc = fmaxf(mloc, __shfl_xor_sync(0xffffffffu, mloc, 1));
            mloc = fmaxf(mloc, __shfl_xor_sync(0xffffffffu, mloc, 2));
            float mnew = fmaxf(mi[rr], mloc);
            float corr = __expf(mi[rr] - mnew);
            float rs = 0.f;
#pragma unroll
            for (int n8 = 0; n8 < 16; n8++) {
                float p0 = __expf(s[n8][2 * rr] - mnew);
                float p1 = __expf(s[n8][2 * rr + 1] - mnew);
                s[n8][2 * rr] = p0; s[n8][2 * rr + 1] = p1;
                rs += p0 + p1;
            }
            rs += __shfl_xor_sync(0xffffffffu, rs, 1);
            rs += __shfl_xor_sync(0xffffffffu, rs, 2);
            li[rr] = li[rr] * corr + rs;
            mi[rr] = mnew;
#pragma unroll
            for (int i = 0; i < 16; i++) {
                o[i][2 * rr]     *= corr;
                o[i][2 * rr + 1] *= corr;
            }
        }

        // O += P @ V : P A-fragments packed directly from S C-fragments
#pragma unroll
        for (int kc = 0; kc < 8; kc++) {
            unsigned a[4];
            a[0] = packh2(s[2 * kc][0],     s[2 * kc][1]);
            a[1] = packh2(s[2 * kc][2],     s[2 * kc][3]);
            a[2] = packh2(s[2 * kc + 1][0], s[2 * kc + 1][1]);
            a[3] = packh2(s[2 * kc + 1][2], s[2 * kc + 1][3]);
#pragma unroll
            for (int p = 0; p < 8; p++) {
                unsigned t4[4];
                ldsm4t(t4, uV + ((kc * 16 + ((lane >> 3) & 1) * 8 + (lane & 7)) * FQS
                                 + p * 16 + (lane >> 4) * 8) * 2);
                unsigned b0[2] = {t4[0], t4[1]};
                unsigned b1[2] = {t4[2], t4[3]};
                mma_f16(o[2 * p], a, b0);
                mma_f16(o[2 * p + 1], a, b1);
            }
        }
        // no trailing barrier: next iteration's top __syncthreads protects bufs
    }

    // epilogue
    float inv0 = 1.f / li[0], inv1 = 1.f / li[1];
    const int row0 = m0 + warp * 16 + (lane >> 2);
#pragma unroll
    for (int n16 = 0; n16 < 16; n16++) {
        int gc = n16 * 8 + 2 * (lane & 3);
        *(__half2*)(O + (size_t)row0 * DIM + h * HD + gc) =
            __floats2half2_rn(o[n16][0] * inv0, o[n16][1] * inv0);
        *(__half2*)(O + (size_t)(row0 + 8) * DIM + h * HD + gc) =
            __floats2half2_rn(o[n16][2] * inv1, o[n16][3] * inv1);
    }
}

// ---------------------------------------------------------------------------
extern "C" void kernel_launch(void* const* d_in, const int* in_sizes, int n_in,
                              void* d_out, int out_size) {
    const float* x    = (const float*)d_in[0];
    const float* cosp = (const float*)d_in[1];
    const float* sinp = (const float*)d_in[2];
    const float* wq   = (const float*)d_in[3];
    const float* wk   = (const float*)d_in[4];
    const float* wv   = (const float*)d_in[5];
    const float* wo   = (const float*)d_in[6];
    const float* qw   = (const float*)d_in[7];
    const float* kw   = (const float*)d_in[8];
    float* out = (float*)d_out;

    __half *xh, *wqh, *wkh, *wvh, *woh, *q, *k, *v, *attn;
    cudaGetSymbolAddress((void**)&xh, g_xh);
    cudaGetSymbolAddress((void**)&wqh, g_wqh);
    cudaGetSymbolAddress((void**)&wkh, g_wkh);
    cudaGetSymbolAddress((void**)&wvh, g_wvh);
    cudaGetSymbolAddress((void**)&woh, g_woh);
    cudaGetSymbolAddress((void**)&q, g_q);
    cudaGetSymbolAddress((void**)&k, g_k);
    cudaGetSymbolAddress((void**)&v, g_v);
    cudaGetSymbolAddress((void**)&attn, g_attn);

    cudaFuncSetAttribute(gemm_f16, cudaFuncAttributeMaxDynamicSharedMemorySize, GSMEM);
    cudaFuncSetAttribute(flash_f16, cudaFuncAttributeMaxDynamicSharedMemorySize, FLASH_SMEM);

    // one merged fp32 -> fp16 conversion (x + 4 weight matrices)
    cvt_all<<<(unsigned)((SEG_WO / 8 + 255) / 256), 256>>>(
        x, wq, wk, wv, wo, xh, wqh, wkh, wvh, woh);

    // fused QKV projection: 24 N-tiles of 256 (16 Q | 4 K | 4 V), f16 out
    gemm_f16<<<dim3(24, S_LEN / 128), 256, GSMEM>>>(
        xh, wqh, wkh, wvh, q, k, v, DIM, KV_DIM, KV_DIM, 16, 20, DIM, 0);

    // merged rmsnorm+rope for q and k
    rmsnorm_rope_kernel<<<dim3(S_LEN, NH + NKV), HD>>>(q, k, qw, kw, cosp, sinp);

    flash_f16<<<dim3(S_LEN / 128, NH), 256, FLASH_SMEM>>>(q, k, v, attn);

    // output projection: 16 N-tiles of 256, f32 out
    gemm_f16<<<dim3(16, S_LEN / 128), 256, GSMEM>>>(
        attn, woh, woh, woh, out, out, out, DIM, DIM, DIM, 16, 20, DIM, 1);
}

// round 10
// speedup vs baseline: 6.8237x; 1.0130x over previous
#include <cuda_runtime.h>
#include <cuda_fp16.h>
#include <math.h>

#define S_LEN 2048
#define DIM 4096
#define NH 32
#define NKV 8
#define HD 128
#define KV_DIM 1024

// f16 scratch (allocation-free rule: __device__ globals)
__device__ __half g_xh[S_LEN * DIM];
__device__ __half g_wqh[DIM * DIM];
__device__ __half g_wkh[KV_DIM * DIM];
__device__ __half g_wvh[KV_DIM * DIM];
__device__ __half g_woh[DIM * DIM];
__device__ __half g_q[S_LEN * DIM];
__device__ __half g_k[S_LEN * KV_DIM];
__device__ __half g_v[S_LEN * KV_DIM];
__device__ __half g_attn[S_LEN * DIM];

// ---------------------------------------------------------------------------
// helpers
// ---------------------------------------------------------------------------
__device__ __forceinline__ unsigned smem_u32(const void* p) {
    unsigned a;
    asm("{ .reg .u64 t; cvta.to.shared.u64 t, %1; cvt.u32.u64 %0, t; }" : "=r"(a) : "l"(p));
    return a;
}

__device__ __forceinline__ void mma_f16(float c[4], const unsigned a[4], const unsigned b[2]) {
    asm volatile(
        "mma.sync.aligned.m16n8k16.row.col.f32.f16.f16.f32 "
        "{%0,%1,%2,%3},{%4,%5,%6,%7},{%8,%9},{%0,%1,%2,%3};"
        : "+f"(c[0]), "+f"(c[1]), "+f"(c[2]), "+f"(c[3])
        : "r"(a[0]), "r"(a[1]), "r"(a[2]), "r"(a[3]), "r"(b[0]), "r"(b[1]));
}

__device__ __forceinline__ void ldsm4(unsigned r[4], unsigned addr) {
    asm volatile("ldmatrix.sync.aligned.m8n8.x4.shared.b16 {%0,%1,%2,%3}, [%4];"
                 : "=r"(r[0]), "=r"(r[1]), "=r"(r[2]), "=r"(r[3]) : "r"(addr));
}

__device__ __forceinline__ void ldsm4t(unsigned r[4], unsigned addr) {
    asm volatile("ldmatrix.sync.aligned.m8n8.x4.trans.shared.b16 {%0,%1,%2,%3}, [%4];"
                 : "=r"(r[0]), "=r"(r[1]), "=r"(r[2]), "=r"(r[3]) : "r"(addr));
}

__device__ __forceinline__ void cpa16(unsigned dst, const void* src) {
    asm volatile("cp.async.cg.shared.global [%0], [%1], 16;" :: "r"(dst), "l"(src));
}

// pack two f32 into f16x2 (lo = a, hi = b), RN
__device__ __forceinline__ unsigned packh2(float a, float b) {
    unsigned r;
    asm("cvt.rn.f16x2.f32 %0, %1, %2;" : "=r"(r) : "f"(b), "f"(a));
    return r;
}

// ---------------------------------------------------------------------------
// single merged fp32 -> fp16 conversion for x, wq, wk, wv, wo
// ---------------------------------------------------------------------------
#define SEG_X  8388608ull
#define SEG_WQ 25165824ull
#define SEG_WK 29360128ull
#define SEG_WV 33554432ull
#define SEG_WO 50331648ull

__global__ void cvt_all(const float* __restrict__ x,  const float* __restrict__ wq,
                        const float* __restrict__ wk, const float* __restrict__ wv,
                        const float* __restrict__ wo,
                        __half* xh, __half* wqh, __half* wkh, __half* wvh, __half* woh) {
    size_t i = ((size_t)blockIdx.x * 256 + threadIdx.x) * 8;
    if (i >= SEG_WO) return;
    const float* s; __half* d; size_t off;
    if (i < SEG_X)       { s = x;  d = xh;  off = i; }
    else if (i < SEG_WQ) { s = wq; d = wqh; off = i - SEG_X; }
    else if (i < SEG_WK) { s = wk; d = wkh; off = i - SEG_WQ; }
    else if (i < SEG_WV) { s = wv; d = wvh; off = i - SEG_WK; }
    else                 { s = wo; d = woh; off = i - SEG_WV; }
    float4 v0 = ((const float4*)(s + off))[0];
    float4 v1 = ((const float4*)(s + off))[1];
    __half2* dp = (__half2*)(d + off);
    dp[0] = __floats2half2_rn(v0.x, v0.y);
    dp[1] = __floats2half2_rn(v0.z, v0.w);
    dp[2] = __floats2half2_rn(v1.x, v1.y);
    dp[3] = __floats2half2_rn(v1.z, v1.w);
}

// ---------------------------------------------------------------------------
// fp16 GEMM: CTA 128x256, K-step 64, 4-stage cp.async pipeline (2 in flight),
// register double-buffered ldmatrix fragments inside each stage.
// ---------------------------------------------------------------------------
#define AST 72                              // 64 + 8 pad (halfs)
#define A_H (128 * AST)
#define B_H (256 * AST)
#define STAGE_BYTES ((A_H + B_H) * 2)       // 55296
#define GSMEM (4 * STAGE_BYTES)             // 221184

__device__ __forceinline__ void g_load_stage(unsigned sbuf, const __half* Ap,
                                             const __half* Bp, int kt, int K, int tid) {
#pragma unroll
    for (int t = 0; t < 4; t++) {           // A: 128 rows x 8 chunks
        int idx = tid + t * 256;
        int row = idx >> 3, ch = idx & 7;
        cpa16(sbuf + (row * AST + ch * 8) * 2, Ap + (size_t)row * K + kt + ch * 8);
    }
#pragma unroll
    for (int t = 0; t < 8; t++) {           // B: 256 rows x 8 chunks
        int idx = tid + t * 256;
        int row = idx >> 3, ch = idx & 7;
        cpa16(sbuf + (A_H + row * AST + ch * 8) * 2, Bp + (size_t)row * K + kt + ch * 8);
    }
}

__global__ __launch_bounds__(256, 1)
void gemm_f16(const __half* __restrict__ Ah,
              const __half* __restrict__ B0, const __half* __restrict__ B1,
              const __half* __restrict__ B2,
              void* C0, void* C1, void* C2,
              int ldc0, int ldc1, int ldc2,
              int n1, int n2, int K, int out_f32) {
    extern __shared__ __align__(16) char smem[];
    const unsigned sbase = smem_u32(smem);
    const int tid = threadIdx.x, lane = tid & 31, warp = tid >> 5;
    const int mbase = (warp >> 2) * 64, nbase = (warp & 3) * 64;
    const int m0 = blockIdx.y * 128;
    const int nt = blockIdx.x;

    const __half* Bsel; void* Csel; int ldc, ncol0;
    if (nt < n1)      { Bsel = B0 + (size_t)nt * 256 * K;        Csel = C0; ldc = ldc0; ncol0 = nt * 256; }
    else if (nt < n2) { Bsel = B1 + (size_t)(nt - n1) * 256 * K; Csel = C1; ldc = ldc1; ncol0 = (nt - n1) * 256; }
    else              { Bsel = B2 + (size_t)(nt - n2) * 256 * K; Csel = C2; ldc = ldc2; ncol0 = (nt - n2) * 256; }
    const __half* Ap = Ah + (size_t)m0 * K;

    float acc[4][8][4];
#pragma unroll
    for (int i = 0; i < 4; i++)
#pragma unroll
        for (int j = 0; j < 8; j++)
#pragma unroll
            for (int r = 0; r < 4; r++) acc[i][j][r] = 0.f;

    const int NS = K / 64;
    g_load_stage(sbase, Ap, Bsel, 0, K, tid);
    asm volatile("cp.async.commit_group;" ::: "memory");
    g_load_stage(sbase + STAGE_BYTES, Ap, Bsel, 64, K, tid);
    asm volatile("cp.async.commit_group;" ::: "memory");
    g_load_stage(sbase + 2 * STAGE_BYTES, Ap, Bsel, 128, K, tid);
    asm volatile("cp.async.commit_group;" ::: "memory");

    for (int s = 0; s < NS; s++) {
        if (s <= NS - 3)      asm volatile("cp.async.wait_group 2;" ::: "memory");
        else if (s == NS - 2) asm volatile("cp.async.wait_group 1;" ::: "memory");
        else                  asm volatile("cp.async.wait_group 0;" ::: "memory");
        __syncthreads();
        if (s + 3 < NS) {
            g_load_stage(sbase + ((s + 3) & 3) * STAGE_BYTES, Ap, Bsel, (s + 3) * 64, K, tid);
            asm volatile("cp.async.commit_group;" ::: "memory");
        }
        const unsigned sA = sbase + (s & 3) * STAGE_BYTES;
        const unsigned sB = sA + A_H * 2;

        // register double-buffered fragments: load kc+1 while mma kc
        unsigned afr[2][4][4], bfr[2][8][2];
#pragma unroll
        for (int mt = 0; mt < 4; mt++)
            ldsm4(afr[0][mt], sA + ((mbase + mt * 16 + (lane & 15)) * AST + (lane >> 4) * 8) * 2);
#pragma unroll
        for (int p = 0; p < 4; p++) {
            unsigned t4[4];
            ldsm4(t4, sB + ((nbase + p * 16 + (lane & 15)) * AST + (lane >> 4) * 8) * 2);
            bfr[0][2 * p][0] = t4[0]; bfr[0][2 * p][1] = t4[2];
            bfr[0][2 * p + 1][0] = t4[1]; bfr[0][2 * p + 1][1] = t4[3];
        }
#pragma unroll
        for (int kc = 0; kc < 4; kc++) {
            const int cur = kc & 1, nxt = cur ^ 1;
            if (kc < 3) {
                const int ko = (kc + 1) * 16;
#pragma unroll
                for (int mt = 0; mt < 4; mt++)
                    ldsm4(afr[nxt][mt], sA + ((mbase + mt * 16 + (lane & 15)) * AST + ko + (lane >> 4) * 8) * 2);
#pragma unroll
                for (int p = 0; p < 4; p++) {
                    unsigned t4[4];
                    ldsm4(t4, sB + ((nbase + p * 16 + (lane & 15)) * AST + ko + (lane >> 4) * 8) * 2);
                    bfr[nxt][2 * p][0] = t4[0]; bfr[nxt][2 * p][1] = t4[2];
                    bfr[nxt][2 * p + 1][0] = t4[1]; bfr[nxt][2 * p + 1][1] = t4[3];
                }
            }
#pragma unroll
            for (int mt = 0; mt < 4; mt++)
#pragma unroll
                for (int n8 = 0; n8 < 8; n8++)
                    mma_f16(acc[mt][n8], afr[cur][mt], bfr[cur][n8]);
        }
        // no bottom sync: next iteration's top __syncthreads orders buffer reuse
    }

#pragma unroll
    for (int mt = 0; mt < 4; mt++) {
        int row0 = m0 + mbase + mt * 16 + (lane >> 2);
#pragma unroll
        for (int n8 = 0; n8 < 8; n8++) {
            int col = ncol0 + nbase + n8 * 8 + 2 * (lane & 3);
            if (out_f32) {
                float* Cp = (float*)Csel;
                *(float2*)(Cp + (size_t)row0 * ldc + col)       = make_float2(acc[mt][n8][0], acc[mt][n8][1]);
                *(float2*)(Cp + (size_t)(row0 + 8) * ldc + col) = make_float2(acc[mt][n8][2], acc[mt][n8][3]);
            } else {
                __half* Cp = (__half*)Csel;
                *(__half2*)(Cp + (size_t)row0 * ldc + col)       = __floats2half2_rn(acc[mt][n8][0], acc[mt][n8][1]);
                *(__half2*)(Cp + (size_t)(row0 + 8) * ldc + col) = __floats2half2_rn(acc[mt][n8][2], acc[mt][n8][3]);
            }
        }
    }
}

// ---------------------------------------------------------------------------
// Merged RMSNorm + RoPE for q and k. grid=(S, NH+NKV).
// ---------------------------------------------------------------------------
__global__ void rmsnorm_rope_kernel(__half* __restrict__ qb, __half* __restrict__ kb,
                                    const float* __restrict__ qw_,
                                    const float* __restrict__ kw_,
                                    const float* __restrict__ cosp,
                                    const float* __restrict__ sinp) {
    const int s = blockIdx.x, hh = blockIdx.y, d = threadIdx.x;
    __half* p;
    const float* w;
    if (hh < NH) { p = qb + (size_t)s * DIM + hh * HD; w = qw_; }
    else         { p = kb + (size_t)s * KV_DIM + (hh - NH) * HD; w = kw_; }
    float v = __half2float(p[d]);
    float sq = v * v;
#pragma unroll
    for (int off = 16; off > 0; off >>= 1)
        sq += __shfl_xor_sync(0xffffffffu, sq, off);
    __shared__ float red[4];
    __shared__ float xs[HD];
    if ((d & 31) == 0) red[d >> 5] = sq;
    __syncthreads();
    float sum = red[0] + red[1] + red[2] + red[3];
    float r = rsqrtf(sum * (1.0f / HD) + 1e-6f);
    float xn = v * r * w[d];
    xs[d] = xn;
    __syncthreads();
    float rot = (d < 64) ? -xs[d + 64] : xs[d - 64];
    p[d] = __float2half_rn(xn * cosp[(size_t)s * HD + d] + rot * sinp[(size_t)s * HD + d]);
}

// ---------------------------------------------------------------------------
// Flash attention, fp16 mma (unchanged from R9).
// ---------------------------------------------------------------------------
#define FQS 136
#define TILE_H (128 * FQS)
#define FLASH_SMEM (5 * TILE_H * 2)

__device__ __forceinline__ void fa_load_kv(unsigned dstK, unsigned dstV,
                                           const __half* Kp, const __half* Vp,
                                           int n0, int kvh, int tid) {
#pragma unroll
    for (int t = 0; t < 8; t++) {
        int idx = tid + t * 256;
        int row = idx >> 4, ch = idx & 15;
        size_t g = (size_t)(n0 + row) * KV_DIM + kvh * HD + ch * 8;
        cpa16(dstK + (row * FQS + ch * 8) * 2, Kp + g);
        cpa16(dstV + (row * FQS + ch * 8) * 2, Vp + g);
    }
}

__global__ __launch_bounds__(256, 1)
void flash_f16(const __half* __restrict__ Q, const __half* __restrict__ K,
               const __half* __restrict__ V, __half* __restrict__ O) {
    extern __shared__ __align__(16) char fsm[];
    const unsigned uQ = smem_u32(fsm);
    const unsigned uK0 = uQ + TILE_H * 2;
    const unsigned uK1 = uK0 + TILE_H * 2;
    const unsigned uV0 = uK1 + TILE_H * 2;
    const unsigned uV1 = uV0 + TILE_H * 2;

    const int tid = threadIdx.x, lane = tid & 31, warp = tid >> 5;
    const int mtb = (gridDim.x - 1) - blockIdx.x;
    const int h = blockIdx.y;
    const int kvh = h >> 2;
    const int m0 = mtb * 128;
    const int NT = mtb + 1;

#pragma unroll
    for (int t = 0; t < 8; t++) {
        int idx = tid + t * 256;
        int row = idx >> 4, ch = idx & 15;
        cpa16(uQ + (row * FQS + ch * 8) * 2,
              Q + (size_t)(m0 + row) * DIM + h * HD + ch * 8);
    }
    fa_load_kv(uK0, uV0, K, V, 0, kvh, tid);
    asm volatile("cp.async.commit_group;" ::: "memory");

    float o[16][4];
    float mi[2] = {-1e30f, -1e30f}, li[2] = {0.f, 0.f};
#pragma unroll
    for (int i = 0; i < 16; i++)
#pragma unroll
        for (int j = 0; j < 4; j++) o[i][j] = 0.f;

    unsigned qf[8][4];

    const float sc = 0.08838834764831845f;
    const int lr = warp * 16 + (lane >> 2);
    const int gr0 = m0 + lr, gr1 = gr0 + 8;

    for (int nt = 0; nt < NT; nt++) {
        const int n0 = nt * 128;
        const unsigned uK = (nt & 1) ? uK1 : uK0;
        const unsigned uV = (nt & 1) ? uV1 : uV0;

        asm volatile("cp.async.wait_group 0;" ::: "memory");
        __syncthreads();

        if (nt == 0) {
#pragma unroll
            for (int kc = 0; kc < 8; kc++)
                ldsm4(qf[kc], uQ + ((warp * 16 + (lane & 15)) * FQS + kc * 16 + (lane >> 4) * 8) * 2);
        }
        if (nt + 1 < NT) {
            fa_load_kv((nt & 1) ? uK0 : uK1, (nt & 1) ? uV0 : uV1,
                       K, V, (nt + 1) * 128, kvh, tid);
            asm volatile("cp.async.commit_group;" ::: "memory");
        }

        float s[16][4];
#pragma unroll
        for (int i = 0; i < 16; i++)
#pragma unroll
            for (int j = 0; j < 4; j++) s[i][j] = 0.f;

#pragma unroll
        for (int kc = 0; kc < 8; kc++) {
#pragma unroll
            for (int p = 0; p < 8; p++) {
                unsigned t4[4];
                ldsm4(t4, uK + ((p * 16 + (lane & 15)) * FQS + kc * 16 + (lane >> 4) * 8) * 2);
                unsigned b0[2] = {t4[0], t4[2]};
                unsigned b1[2] = {t4[1], t4[3]};
                mma_f16(s[2 * p], qf[kc], b0);
                mma_f16(s[2 * p + 1], qf[kc], b1);
            }
        }

        const bool diag = (nt == NT - 1);
#pragma unroll
        for (int n8 = 0; n8 < 16; n8++) {
            int gc = n0 + n8 * 8 + 2 * (lane & 3);
            s[n8][0] *= sc; s[n8][1] *= sc; s[n8][2] *= sc; s[n8][3] *= sc;
            if (diag) {
                if (gc     > gr0) s[n8][0] = -1e30f;
                if (gc + 1 > gr0) s[n8][1] = -1e30f;
                if (gc     > gr1) s[n8][2] = -1e30f;
                if (gc + 1 > gr1) s[n8][3] = -1e30f;
            }
        }

#pragma unroll
        for (int rr = 0; rr < 2; rr++) {
            float mloc = -1e30f;
#pragma unroll
            for (int n8 = 0; n8 < 16; n8++)
                mloc = fmaxf(mloc, fmaxf(s[n8][2 * rr], s[n8][2 * rr + 1]));
            mloc = fmaxf(mloc, __shfl_xor_sync(0xffffffffu, mloc, 1));
            mloc = fmaxf(mloc, __shfl_xor_sync(0xffffffffu, mloc, 2));
            float mnew = fmaxf(mi[rr], mloc);
            float corr = __expf(mi[rr] - mnew);
            float rs = 0.f;
#pragma unroll
            for (int n8 = 0; n8 < 16; n8++) {
                float p0 = __expf(s[n8][2 * rr] - mnew);
                float p1 = __expf(s[n8][2 * rr + 1] - mnew);
                s[n8][2 * rr] = p0; s[n8][2 * rr + 1] = p1;
                rs += p0 + p1;
            }
            rs += __shfl_xor_sync(0xffffffffu, rs, 1);
            rs += __shfl_xor_sync(0xffffffffu, rs, 2);
            li[rr] = li[rr] * corr + rs;
            mi[rr] = mnew;
#pragma unroll
            for (int i = 0; i < 16; i++) {
                o[i][2 * rr]     *= corr;
                o[i][2 * rr + 1] *= corr;
            }
        }

#pragma unroll
        for (int kc = 0; kc < 8; kc++) {
            unsigned a[4];
            a[0] = packh2(s[2 * kc][0],     s[2 * kc][1]);
            a[1] = packh2(s[2 * kc][2],     s[2 * kc][3]);
            a[2] = packh2(s[2 * kc + 1][0], s[2 * kc + 1][1]);
            a[3] = packh2(s[2 * kc + 1][2], s[2 * kc + 1][3]);
#pragma unroll
            for (int p = 0; p < 8; p++) {
                unsigned t4[4];
                ldsm4t(t4, uV + ((kc * 16 + ((lane >> 3) & 1) * 8 + (lane & 7)) * FQS
                                 + p * 16 + (lane >> 4) * 8) * 2);
                unsigned b0[2] = {t4[0], t4[1]};
                unsigned b1[2] = {t4[2], t4[3]};
                mma_f16(o[2 * p], a, b0);
                mma_f16(o[2 * p + 1], a, b1);
            }
        }
    }

    float inv0 = 1.f / li[0], inv1 = 1.f / li[1];
    const int row0 = m0 + warp * 16 + (lane >> 2);
#pragma unroll
    for (int n16 = 0; n16 < 16; n16++) {
        int gc = n16 * 8 + 2 * (lane & 3);
        *(__half2*)(O + (size_t)row0 * DIM + h * HD + gc) =
            __floats2half2_rn(o[n16][0] * inv0, o[n16][1] * inv0);
        *(__half2*)(O + (size_t)(row0 + 8) * DIM + h * HD + gc) =
            __floats2half2_rn(o[n16][2] * inv1, o[n16][3] * inv1);
    }
}

// ---------------------------------------------------------------------------
extern "C" void kernel_launch(void* const* d_in, const int* in_sizes, int n_in,
                              void* d_out, int out_size) {
    const float* x    = (const float*)d_in[0];
    const float* cosp = (const float*)d_in[1];
    const float* sinp = (const float*)d_in[2];
    const float* wq   = (const float*)d_in[3];
    const float* wk   = (const float*)d_in[4];
    const float* wv   = (const float*)d_in[5];
    const float* wo   = (const float*)d_in[6];
    const float* qw   = (const float*)d_in[7];
    const float* kw   = (const float*)d_in[8];
    float* out = (float*)d_out;

    __half *xh, *wqh, *wkh, *wvh, *woh, *q, *k, *v, *attn;
    cudaGetSymbolAddress((void**)&xh, g_xh);
    cudaGetSymbolAddress((void**)&wqh, g_wqh);
    cudaGetSymbolAddress((void**)&wkh, g_wkh);
    cudaGetSymbolAddress((void**)&wvh, g_wvh);
    cudaGetSymbolAddress((void**)&woh, g_woh);
    cudaGetSymbolAddress((void**)&q, g_q);
    cudaGetSymbolAddress((void**)&k, g_k);
    cudaGetSymbolAddress((void**)&v, g_v);
    cudaGetSymbolAddress((void**)&attn, g_attn);

    cudaFuncSetAttribute(gemm_f16, cudaFuncAttributeMaxDynamicSharedMemorySize, GSMEM);
    cudaFuncSetAttribute(flash_f16, cudaFuncAttributeMaxDynamicSharedMemorySize, FLASH_SMEM);

    // one merged fp32 -> fp16 conversion (x + 4 weight matrices)
    cvt_all<<<(unsigned)((SEG_WO / 8 + 255) / 256), 256>>>(
        x, wq, wk, wv, wo, xh, wqh, wkh, wvh, woh);

    // fused QKV projection: 24 N-tiles of 256 (16 Q | 4 K | 4 V), f16 out
    gemm_f16<<<dim3(24, S_LEN / 128), 256, GSMEM>>>(
        xh, wqh, wkh, wvh, q, k, v, DIM, KV_DIM, KV_DIM, 16, 20, DIM, 0);

    // merged rmsnorm+rope for q and k
    rmsnorm_rope_kernel<<<dim3(S_LEN, NH + NKV), HD>>>(q, k, qw, kw, cosp, sinp);

    flash_f16<<<dim3(S_LEN / 128, NH), 256, FLASH_SMEM>>>(q, k, v, attn);

    // output projection: 16 N-tiles of 256, f32 out
    gemm_f16<<<dim3(16, S_LEN / 128), 256, GSMEM>>>(
        attn, woh, woh, woh, out, out, out, DIM, DIM, DIM, 16, 20, DIM, 1);
}